// round 1
// baseline (speedup 1.0000x reference)
#include <cuda_runtime.h>
#include <math.h>

// ---------------- problem constants ----------------
#define NN    50000   // nodes
#define IND   1024    // in dim
#define EE    100000  // edges
#define NREL  40
#define NH    4       // heads
#define OD    200     // out dim per head
#define HIDD  800     // NH*OD
#define BB    8192    // batch of triples
#define NEG_SLOPE 0.2f

typedef int idx_t;    // jax default (x64 disabled) canonicalizes int64 -> int32

// ---------------- scratch (device globals; no allocation allowed) ----------------
__device__ float g_h[(size_t)NN * HIDD];      // 160 MB : h = node_emb @ W
__device__ float g_out[(size_t)NN * HIDD];    // 160 MB : refined (aggregated + bias)
__device__ float g_ssrc[NN * NH];             // per-node dot(h, a_src)
__device__ float g_sdst[NN * NH];             // per-node dot(h, a_dst)
__device__ float g_srel[NREL * NH];           // per-rel  dot(rel_feat, a_rel)
__device__ float g_segmax[NN * NH];
__device__ float g_denom[NN * NH];
__device__ float g_eedge[EE * NH];            // logits, then exp weights

// ---------------- helpers ----------------
__device__ __forceinline__ void atomicMaxFloat(float* addr, float val) {
    if (val >= 0.0f) {
        atomicMax((int*)addr, __float_as_int(val));
    } else {
        atomicMin((unsigned int*)addr, (unsigned int)__float_as_int(val));
    }
}

__device__ __forceinline__ float warpReduceSum(float v) {
    #pragma unroll
    for (int o = 16; o > 0; o >>= 1) v += __shfl_xor_sync(0xFFFFFFFFu, v, o);
    return v;
}

// ---------------- 1) GEMM: g_h = node_emb[NN,IND] @ W[IND,HIDD] ----------------
#define BM 128
#define BN 64
#define BK 8

__global__ __launch_bounds__(256) void gemm_kernel(const float* __restrict__ A,
                                                   const float* __restrict__ B) {
    __shared__ float As[BK][BM];
    __shared__ float Bs[BK][BN];

    const int tid = threadIdx.x;
    const int tx = tid & 15;          // 0..15 -> 4 cols each
    const int ty = tid >> 4;          // 0..15 -> 8 rows each
    const int rowBase = blockIdx.y * BM;
    const int colBase = blockIdx.x * BN;

    // A tile load mapping: 128x8 floats, 256 thr -> one float4 each
    const int arow = tid >> 1;            // 0..127
    const int acol = (tid & 1) * 4;       // 0 or 4
    // B tile load mapping: 8x64 floats, 256 thr -> one float2 each
    const int brow = tid >> 5;            // 0..7
    const int bcol = (tid & 31) * 2;      // 0..62

    float acc[8][4];
    #pragma unroll
    for (int i = 0; i < 8; i++)
        #pragma unroll
        for (int j = 0; j < 4; j++) acc[i][j] = 0.0f;

    for (int k0 = 0; k0 < IND; k0 += BK) {
        float4 av = make_float4(0.f, 0.f, 0.f, 0.f);
        const int gr = rowBase + arow;
        if (gr < NN) av = *(const float4*)(A + (size_t)gr * IND + k0 + acol);
        As[acol + 0][arow] = av.x;
        As[acol + 1][arow] = av.y;
        As[acol + 2][arow] = av.z;
        As[acol + 3][arow] = av.w;

        float2 bv = make_float2(0.f, 0.f);
        const int gc = colBase + bcol;
        if (gc < HIDD) bv = *(const float2*)(B + (size_t)(k0 + brow) * HIDD + gc);
        Bs[brow][bcol]     = bv.x;
        Bs[brow][bcol + 1] = bv.y;

        __syncthreads();

        #pragma unroll
        for (int kk = 0; kk < BK; kk++) {
            float a[8], b[4];
            float4 a0 = *(const float4*)&As[kk][ty * 8];
            float4 a1 = *(const float4*)&As[kk][ty * 8 + 4];
            a[0]=a0.x; a[1]=a0.y; a[2]=a0.z; a[3]=a0.w;
            a[4]=a1.x; a[5]=a1.y; a[6]=a1.z; a[7]=a1.w;
            float4 b0 = *(const float4*)&Bs[kk][tx * 4];
            b[0]=b0.x; b[1]=b0.y; b[2]=b0.z; b[3]=b0.w;
            #pragma unroll
            for (int i = 0; i < 8; i++)
                #pragma unroll
                for (int j = 0; j < 4; j++)
                    acc[i][j] = fmaf(a[i], b[j], acc[i][j]);
        }
        __syncthreads();
    }

    #pragma unroll
    for (int i = 0; i < 8; i++) {
        const int r = rowBase + ty * 8 + i;
        if (r >= NN) continue;
        #pragma unroll
        for (int j = 0; j < 4; j++) {
            const int c = colBase + tx * 4 + j;
            if (c < HIDD) g_h[(size_t)r * HIDD + c] = acc[i][j];
        }
    }
}

// ---------------- 2) init: segmax=-inf, denom=0, out = bias (broadcast) ----------------
__global__ void init_kernel(const float* __restrict__ bias) {
    const long long i = (long long)blockIdx.x * blockDim.x + threadIdx.x;
    if (i < (long long)NN * NH) {
        g_segmax[i] = -INFINITY;
        g_denom[i] = 0.0f;
    }
    if (i < (long long)NN * HIDD) {
        g_out[i] = bias[(int)(i % HIDD)];
    }
}

// ---------------- 3) per-node attention dots: s_src / s_dst ----------------
__global__ __launch_bounds__(128) void node_dots_kernel(const float* __restrict__ a_src,
                                                        const float* __restrict__ a_dst) {
    const int n = blockIdx.x;
    const int w = threadIdx.x >> 5;   // head
    const int lane = threadIdx.x & 31;
    const float* hr = g_h + (size_t)n * HIDD + w * OD;
    float s1 = 0.f, s2 = 0.f;
    for (int d = lane; d < OD; d += 32) {
        const float v = hr[d];
        s1 = fmaf(v, a_src[w * OD + d], s1);
        s2 = fmaf(v, a_dst[w * OD + d], s2);
    }
    s1 = warpReduceSum(s1);
    s2 = warpReduceSum(s2);
    if (lane == 0) {
        g_ssrc[n * NH + w] = s1;
        g_sdst[n * NH + w] = s2;
    }
}

// ---------------- 4) per-relation dots: s_rel ----------------
__global__ __launch_bounds__(256) void rel_dots_kernel(const float* __restrict__ rel_feat,
                                                       const float* __restrict__ a_rel) {
    const int gw = blockIdx.x * 8 + (threadIdx.x >> 5);
    const int lane = threadIdx.x & 31;
    if (gw >= NREL * NH) return;
    const int r = gw >> 2, hh = gw & 3;
    float s = 0.f;
    for (int d = lane; d < OD; d += 32)
        s = fmaf(rel_feat[(size_t)r * HIDD + hh * OD + d], a_rel[hh * OD + d], s);
    s = warpReduceSum(s);
    if (lane == 0) g_srel[r * NH + hh] = s;
}

// ---------------- 5) edge logits + leaky relu + segment max ----------------
__global__ void edge_logits_kernel(const idx_t* __restrict__ eidx,
                                   const idx_t* __restrict__ etype) {
    const int i = blockIdx.x * blockDim.x + threadIdx.x;
    if (i >= EE * NH) return;
    const int e = i >> 2, hh = i & 3;
    const idx_t src = eidx[e];
    const idx_t dst = eidx[EE + e];
    const idx_t t = etype[e];
    float l = g_ssrc[src * NH + hh] + g_sdst[dst * NH + hh] + g_srel[t * NH + hh];
    l = (l > 0.0f) ? l : NEG_SLOPE * l;
    g_eedge[i] = l;
    atomicMaxFloat(&g_segmax[dst * NH + hh], l);
}

// ---------------- 6) exp + segment sum ----------------
__global__ void edge_exp_kernel(const idx_t* __restrict__ eidx) {
    const int i = blockIdx.x * blockDim.x + threadIdx.x;
    if (i >= EE * NH) return;
    const int e = i >> 2, hh = i & 3;
    const idx_t dst = eidx[EE + e];
    const float w = __expf(g_eedge[i] - g_segmax[dst * NH + hh]);
    g_eedge[i] = w;
    atomicAdd(&g_denom[dst * NH + hh], w);
}

// ---------------- 7) weighted scatter-aggregate: out[dst] += alpha * h[src] ----------------
__global__ __launch_bounds__(256) void aggregate_kernel(const idx_t* __restrict__ eidx) {
    const int e = blockIdx.x * 8 + (threadIdx.x >> 5);
    const int lane = threadIdx.x & 31;
    if (e >= EE) return;
    const idx_t src = eidx[e];
    const idx_t dst = eidx[EE + e];
    const float4* __restrict__ hs = (const float4*)(g_h + (size_t)src * HIDD);
    float* __restrict__ od = g_out + (size_t)dst * HIDD;
    #pragma unroll
    for (int hh = 0; hh < NH; hh++) {
        const float alpha = g_eedge[e * NH + hh] / g_denom[dst * NH + hh];
        const int base = hh * (OD / 4);   // 50 float4 per head
        for (int i = lane; i < OD / 4; i += 32) {
            const float4 v = hs[base + i];
            float* p = od + (base + i) * 4;
            atomicAdd(p + 0, alpha * v.x);
            atomicAdd(p + 1, alpha * v.y);
            atomicAdd(p + 2, alpha * v.z);
            atomicAdd(p + 3, alpha * v.w);
        }
    }
}

// ---------------- 8) DistMult scoring ----------------
__global__ __launch_bounds__(256) void distmult_kernel(const float* __restrict__ rel_emb,
                                                       const idx_t* __restrict__ src_ids,
                                                       const idx_t* __restrict__ rel_ids,
                                                       const idx_t* __restrict__ dst_ids,
                                                       float* __restrict__ out) {
    const int b = blockIdx.x * 8 + (threadIdx.x >> 5);
    const int lane = threadIdx.x & 31;
    if (b >= BB) return;
    const idx_t s = src_ids[b];
    const idx_t r = rel_ids[b];
    const idx_t d = dst_ids[b];
    const float4* sv = (const float4*)(g_out + (size_t)s * HIDD);
    const float4* rv = (const float4*)(rel_emb + (size_t)r * HIDD);
    const float4* dv = (const float4*)(g_out + (size_t)d * HIDD);
    float acc = 0.f;
    for (int i = lane; i < HIDD / 4; i += 32) {
        const float4 a = sv[i], bb = rv[i], c = dv[i];
        acc += a.x * bb.x * c.x + a.y * bb.y * c.y + a.z * bb.z * c.z + a.w * bb.w * c.w;
    }
    acc = warpReduceSum(acc);
    if (lane == 0) out[b] = acc;
}

// ---------------- launch ----------------
extern "C" void kernel_launch(void* const* d_in, const int* in_sizes, int n_in,
                              void* d_out, int out_size) {
    const float* node_emb = (const float*)d_in[0];
    const float* W        = (const float*)d_in[1];
    const float* bias     = (const float*)d_in[2];
    const float* a_src    = (const float*)d_in[3];
    const float* a_dst    = (const float*)d_in[4];
    const float* a_rel    = (const float*)d_in[5];
    const float* rel_feat = (const float*)d_in[6];
    const float* rel_emb  = (const float*)d_in[7];
    const idx_t* eidx     = (const idx_t*)d_in[8];
    const idx_t* etype    = (const idx_t*)d_in[9];
    const idx_t* src_ids  = (const idx_t*)d_in[10];
    const idx_t* rel_ids  = (const idx_t*)d_in[11];
    const idx_t* dst_ids  = (const idx_t*)d_in[12];
    float* scores = (float*)d_out;

    // 1) GEMM
    {
        dim3 grid((HIDD + BN - 1) / BN, (NN + BM - 1) / BM);
        gemm_kernel<<<grid, 256>>>(node_emb, W);
    }
    // 2) init segmax/denom/out
    {
        const long long total = (long long)NN * HIDD;
        init_kernel<<<(unsigned)((total + 255) / 256), 256>>>(bias);
    }
    // 3) per-node dots
    node_dots_kernel<<<NN, 128>>>(a_src, a_dst);
    // 4) per-rel dots
    rel_dots_kernel<<<(NREL * NH + 7) / 8, 256>>>(rel_feat, a_rel);
    // 5) logits + segmax
    edge_logits_kernel<<<(EE * NH + 255) / 256, 256>>>(eidx, etype);
    // 6) exp + denom
    edge_exp_kernel<<<(EE * NH + 255) / 256, 256>>>(eidx);
    // 7) aggregate
    aggregate_kernel<<<(EE + 7) / 8, 256>>>(eidx);
    // 8) DistMult
    distmult_kernel<<<(BB + 7) / 8, 256>>>(rel_emb, src_ids, rel_ids, dst_ids, scores);
}

// round 3
// speedup vs baseline: 2.1273x; 2.1273x over previous
#include <cuda_runtime.h>
#include <math.h>
#include <stdint.h>

// ---------------- problem constants ----------------
#define NN    50000   // nodes
#define IND   1024    // in dim
#define EE    100000  // edges
#define NREL  40
#define NH    4       // heads
#define OD    200     // out dim per head
#define HIDD  800     // NH*OD
#define BB    8192    // batch of triples
#define NEG_SLOPE 0.2f

typedef int idx_t;

// ---------------- scratch (device globals) ----------------
__device__ float g_h[(size_t)NN * HIDD];      // h rows (only needed rows written)
__device__ float g_out[(size_t)NN * HIDD];    // refined
__device__ float g_psrc[IND * NH];            // W @ a_src folded  [k][h]
__device__ float g_pdst[IND * NH];            // W @ a_dst folded  [k][h]
__device__ float g_ssrc[NN * NH];
__device__ float g_sdst[NN * NH];
__device__ float g_srel[NREL * NH];
__device__ float g_segmax[NN * NH];
__device__ float g_denom[NN * NH];
__device__ float g_eedge[EE * NH];
__device__ int   g_flagS[NN];                 // node in scoring set S
__device__ int   g_needH[NN];                 // dedup flag for row list
__device__ int   g_rows[NN];                  // compacted list of rows needing h
__device__ int   g_cnt;                       // number of rows in list

// ---------------- helpers ----------------
__device__ __forceinline__ void atomicMaxFloat(float* addr, float val) {
    if (val >= 0.0f) atomicMax((int*)addr, __float_as_int(val));
    else atomicMin((unsigned int*)addr, (unsigned int)__float_as_int(val));
}
__device__ __forceinline__ float warpReduceSum(float v) {
    #pragma unroll
    for (int o = 16; o > 0; o >>= 1) v += __shfl_xor_sync(0xFFFFFFFFu, v, o);
    return v;
}
// ---- packed f32x2 (FFMA2) helpers ----
__device__ __forceinline__ unsigned long long dup2(float x) {
    unsigned long long r;
    asm("mov.b64 %0, {%1, %1};" : "=l"(r) : "r"(__float_as_uint(x)));
    return r;
}
__device__ __forceinline__ unsigned long long pack2(float lo, float hi) {
    unsigned long long r;
    asm("mov.b64 %0, {%1, %2};" : "=l"(r) : "r"(__float_as_uint(lo)), "r"(__float_as_uint(hi)));
    return r;
}
__device__ __forceinline__ void ffma2(unsigned long long& d, unsigned long long a, unsigned long long b) {
    asm("fma.rn.f32x2 %0, %1, %2, %0;" : "+l"(d) : "l"(a), "l"(b));
}
__device__ __forceinline__ void unpack2(unsigned long long v, float& lo, float& hi) {
    unsigned int a, b;
    asm("mov.b64 {%0, %1}, %2;" : "=r"(a), "=r"(b) : "l"(v));
    lo = __uint_as_float(a); hi = __uint_as_float(b);
}

// ---------------- 0) reset / init ----------------
__global__ void init_kernel(const float* __restrict__ bias) {
    const long long i = (long long)blockIdx.x * blockDim.x + threadIdx.x;
    if (i == 0) g_cnt = 0;
    if (i < NN) { g_flagS[i] = 0; g_needH[i] = 0; }
    if (i < (long long)NN * NH) {
        g_segmax[i] = -INFINITY;
        g_denom[i] = 0.0f;
    }
    if (i < (long long)NN * HIDD) g_out[i] = bias[(int)(i % HIDD)];
}

// ---------------- 1) mark scoring set S ----------------
__global__ void mark_s_kernel(const idx_t* __restrict__ src_ids,
                              const idx_t* __restrict__ dst_ids) {
    const int i = blockIdx.x * blockDim.x + threadIdx.x;
    if (i >= BB) return;
    g_flagS[src_ids[i]] = 1;
    g_flagS[dst_ids[i]] = 1;
}

// ---------------- 2) build list of rows needing h ----------------
__global__ void build_list_kernel(const idx_t* __restrict__ eidx) {
    const int e = blockIdx.x * blockDim.x + threadIdx.x;
    if (e >= EE) return;
    const idx_t dst = eidx[EE + e];
    if (!g_flagS[dst]) return;
    const idx_t src = eidx[e];
    if (atomicExch(&g_needH[src], 1) == 0) {
        const int p = atomicAdd(&g_cnt, 1);
        g_rows[p] = src;
    }
}

// ---------------- 3) fold a_src/a_dst through W: p[k][h] ----------------
__global__ __launch_bounds__(128) void proj_kernel(const float* __restrict__ W,
                                                   const float* __restrict__ a_src,
                                                   const float* __restrict__ a_dst) {
    const int k = blockIdx.x;
    const int h = threadIdx.x >> 5;
    const int lane = threadIdx.x & 31;
    float s1 = 0.f, s2 = 0.f;
    for (int d = lane; d < OD; d += 32) {
        const float w = W[(size_t)k * HIDD + h * OD + d];
        s1 = fmaf(w, a_src[h * OD + d], s1);
        s2 = fmaf(w, a_dst[h * OD + d], s2);
    }
    s1 = warpReduceSum(s1);
    s2 = warpReduceSum(s2);
    if (lane == 0) {
        g_psrc[k * NH + h] = s1;
        g_pdst[k * NH + h] = s2;
    }
}

// ---------------- 4) s_src/s_dst GEMV: node_emb @ p ----------------
__global__ __launch_bounds__(256) void svec_kernel(const float* __restrict__ node_emb) {
    __shared__ float4 ps[IND], pd[IND];
    const int tid = threadIdx.x;
    for (int i = tid; i < IND; i += 256) {
        ps[i] = ((const float4*)g_psrc)[i];
        pd[i] = ((const float4*)g_pdst)[i];
    }
    __syncthreads();
    const int n = blockIdx.x * 8 + (tid >> 5);
    const int lane = tid & 31;
    if (n >= NN) return;
    const float* row = node_emb + (size_t)n * IND;
    float4 s1 = make_float4(0.f, 0.f, 0.f, 0.f);
    float4 s2 = make_float4(0.f, 0.f, 0.f, 0.f);
    #pragma unroll 4
    for (int j = 0; j < IND / 32; j++) {
        const int k = lane + 32 * j;
        const float v = row[k];
        const float4 p1 = ps[k], p2 = pd[k];
        s1.x = fmaf(v, p1.x, s1.x); s1.y = fmaf(v, p1.y, s1.y);
        s1.z = fmaf(v, p1.z, s1.z); s1.w = fmaf(v, p1.w, s1.w);
        s2.x = fmaf(v, p2.x, s2.x); s2.y = fmaf(v, p2.y, s2.y);
        s2.z = fmaf(v, p2.z, s2.z); s2.w = fmaf(v, p2.w, s2.w);
    }
    s1.x = warpReduceSum(s1.x); s1.y = warpReduceSum(s1.y);
    s1.z = warpReduceSum(s1.z); s1.w = warpReduceSum(s1.w);
    s2.x = warpReduceSum(s2.x); s2.y = warpReduceSum(s2.y);
    s2.z = warpReduceSum(s2.z); s2.w = warpReduceSum(s2.w);
    if (lane == 0) {
        ((float4*)g_ssrc)[n] = s1;
        ((float4*)g_sdst)[n] = s2;
    }
}

// ---------------- 5) per-relation dots ----------------
__global__ __launch_bounds__(256) void rel_dots_kernel(const float* __restrict__ rel_feat,
                                                       const float* __restrict__ a_rel) {
    const int gw = blockIdx.x * 8 + (threadIdx.x >> 5);
    const int lane = threadIdx.x & 31;
    if (gw >= NREL * NH) return;
    const int r = gw >> 2, hh = gw & 3;
    float s = 0.f;
    for (int d = lane; d < OD; d += 32)
        s = fmaf(rel_feat[(size_t)r * HIDD + hh * OD + d], a_rel[hh * OD + d], s);
    s = warpReduceSum(s);
    if (lane == 0) g_srel[r * NH + hh] = s;
}

// ---------------- 6) gather-GEMM (FFMA2): g_h[rows] = node_emb[rows] @ W ----------------
#define BM 128
#define BN 64
#define BK 8

__global__ __launch_bounds__(256) void gemm_rows_kernel(const float* __restrict__ A,
                                                        const float* __restrict__ B) {
    const int R = *(volatile int*)&g_cnt;
    const int rowBase = blockIdx.y * BM;
    if (rowBase >= R) return;

    __shared__ float As[BK][BM];
    __shared__ float Bs[BK][BN];

    const int tid = threadIdx.x;
    const int tx = tid & 15;          // 0..15 -> 4 cols each
    const int ty = tid >> 4;          // 0..15 -> 8 rows each
    const int colBase = blockIdx.x * BN;

    // A tile load mapping: 128 rows x 8 k, 256 thr -> one float4 each
    const int arow = tid >> 1;
    const int acol = (tid & 1) * 4;
    const int lr = rowBase + arow;
    const float* aptr = nullptr;
    if (lr < R) aptr = A + (size_t)g_rows[lr] * IND + acol;
    // B tile load mapping: 8 k x 64 cols, 256 thr -> one float2 each
    const int brow = tid >> 5;
    const int bcol = (tid & 31) * 2;
    const int gc = colBase + bcol;

    unsigned long long acc[4][4];     // [row-pair][col] packed f32x2
    #pragma unroll
    for (int i = 0; i < 4; i++)
        #pragma unroll
        for (int j = 0; j < 4; j++) acc[i][j] = 0ull;

    for (int k0 = 0; k0 < IND; k0 += BK) {
        float4 av = make_float4(0.f, 0.f, 0.f, 0.f);
        if (aptr) av = *(const float4*)(aptr + k0);
        As[acol + 0][arow] = av.x;
        As[acol + 1][arow] = av.y;
        As[acol + 2][arow] = av.z;
        As[acol + 3][arow] = av.w;

        float2 bv = make_float2(0.f, 0.f);
        if (gc < HIDD) bv = *(const float2*)(B + (size_t)(k0 + brow) * HIDD + gc);
        Bs[brow][bcol]     = bv.x;
        Bs[brow][bcol + 1] = bv.y;

        __syncthreads();

        #pragma unroll
        for (int kk = 0; kk < BK; kk++) {
            const float2* ar2 = (const float2*)&As[kk][ty * 8];
            const float4 b4 = *(const float4*)&Bs[kk][tx * 4];
            unsigned long long bd[4];
            bd[0] = dup2(b4.x); bd[1] = dup2(b4.y);
            bd[2] = dup2(b4.z); bd[3] = dup2(b4.w);
            #pragma unroll
            for (int i = 0; i < 4; i++) {
                const float2 a2f = ar2[i];
                const unsigned long long a2 = pack2(a2f.x, a2f.y);
                ffma2(acc[i][0], a2, bd[0]);
                ffma2(acc[i][1], a2, bd[1]);
                ffma2(acc[i][2], a2, bd[2]);
                ffma2(acc[i][3], a2, bd[3]);
            }
        }
        __syncthreads();
    }

    // store: row pair i covers local rows ty*8+2i, ty*8+2i+1
    #pragma unroll
    for (int i = 0; i < 4; i++) {
        #pragma unroll
        for (int half = 0; half < 2; half++) {
            const int lrr = rowBase + ty * 8 + 2 * i + half;
            if (lrr >= R) continue;
            float* orow = g_h + (size_t)g_rows[lrr] * HIDD;
            #pragma unroll
            for (int j = 0; j < 4; j++) {
                const int c = colBase + tx * 4 + j;
                if (c < HIDD) {
                    float lo, hi;
                    unpack2(acc[i][j], lo, hi);
                    orow[c] = half ? hi : lo;
                }
            }
        }
    }
}

// ---------------- 7) edge logits + segment max (filtered) ----------------
__global__ void edge_logits_kernel(const idx_t* __restrict__ eidx,
                                   const idx_t* __restrict__ etype) {
    const int i = blockIdx.x * blockDim.x + threadIdx.x;
    if (i >= EE * NH) return;
    const int e = i >> 2, hh = i & 3;
    const idx_t dst = eidx[EE + e];
    if (!g_flagS[dst]) return;
    const idx_t src = eidx[e];
    const idx_t t = etype[e];
    float l = g_ssrc[src * NH + hh] + g_sdst[dst * NH + hh] + g_srel[t * NH + hh];
    l = (l > 0.0f) ? l : NEG_SLOPE * l;
    g_eedge[i] = l;
    atomicMaxFloat(&g_segmax[dst * NH + hh], l);
}

// ---------------- 8) exp + segment sum (filtered) ----------------
__global__ void edge_exp_kernel(const idx_t* __restrict__ eidx) {
    const int i = blockIdx.x * blockDim.x + threadIdx.x;
    if (i >= EE * NH) return;
    const int e = i >> 2, hh = i & 3;
    const idx_t dst = eidx[EE + e];
    if (!g_flagS[dst]) return;
    const float w = __expf(g_eedge[i] - g_segmax[dst * NH + hh]);
    g_eedge[i] = w;
    atomicAdd(&g_denom[dst * NH + hh], w);
}

// ---------------- 9) weighted scatter-aggregate (filtered) ----------------
__global__ __launch_bounds__(256) void aggregate_kernel(const idx_t* __restrict__ eidx) {
    const int e = blockIdx.x * 8 + (threadIdx.x >> 5);
    const int lane = threadIdx.x & 31;
    if (e >= EE) return;
    const idx_t dst = eidx[EE + e];
    if (!g_flagS[dst]) return;
    const idx_t src = eidx[e];
    const float4* __restrict__ hs = (const float4*)(g_h + (size_t)src * HIDD);
    float* __restrict__ od = g_out + (size_t)dst * HIDD;
    #pragma unroll
    for (int hh = 0; hh < NH; hh++) {
        const float alpha = g_eedge[e * NH + hh] / g_denom[dst * NH + hh];
        const int base = hh * (OD / 4);
        for (int i = lane; i < OD / 4; i += 32) {
            const float4 v = hs[base + i];
            float* p = od + (base + i) * 4;
            atomicAdd(p + 0, alpha * v.x);
            atomicAdd(p + 1, alpha * v.y);
            atomicAdd(p + 2, alpha * v.z);
            atomicAdd(p + 3, alpha * v.w);
        }
    }
}

// ---------------- 10) DistMult scoring ----------------
__global__ __launch_bounds__(256) void distmult_kernel(const float* __restrict__ rel_emb,
                                                       const idx_t* __restrict__ src_ids,
                                                       const idx_t* __restrict__ rel_ids,
                                                       const idx_t* __restrict__ dst_ids,
                                                       float* __restrict__ out) {
    const int b = blockIdx.x * 8 + (threadIdx.x >> 5);
    const int lane = threadIdx.x & 31;
    if (b >= BB) return;
    const idx_t s = src_ids[b];
    const idx_t r = rel_ids[b];
    const idx_t d = dst_ids[b];
    const float4* sv = (const float4*)(g_out + (size_t)s * HIDD);
    const float4* rv = (const float4*)(rel_emb + (size_t)r * HIDD);
    const float4* dv = (const float4*)(g_out + (size_t)d * HIDD);
    float acc = 0.f;
    for (int i = lane; i < HIDD / 4; i += 32) {
        const float4 a = sv[i], bb = rv[i], c = dv[i];
        acc += a.x * bb.x * c.x + a.y * bb.y * c.y + a.z * bb.z * c.z + a.w * bb.w * c.w;
    }
    acc = warpReduceSum(acc);
    if (lane == 0) out[b] = acc;
}

// ---------------- launch ----------------
extern "C" void kernel_launch(void* const* d_in, const int* in_sizes, int n_in,
                              void* d_out, int out_size) {
    const float* node_emb = (const float*)d_in[0];
    const float* W        = (const float*)d_in[1];
    const float* bias     = (const float*)d_in[2];
    const float* a_src    = (const float*)d_in[3];
    const float* a_dst    = (const float*)d_in[4];
    const float* a_rel    = (const float*)d_in[5];
    const float* rel_feat = (const float*)d_in[6];
    const float* rel_emb  = (const float*)d_in[7];
    const idx_t* eidx     = (const idx_t*)d_in[8];
    const idx_t* etype    = (const idx_t*)d_in[9];
    const idx_t* src_ids  = (const idx_t*)d_in[10];
    const idx_t* rel_ids  = (const idx_t*)d_in[11];
    const idx_t* dst_ids  = (const idx_t*)d_in[12];
    float* scores = (float*)d_out;

    // 0) reset flags/counters, segmax/denom, out=bias
    {
        const long long total = (long long)NN * HIDD;
        init_kernel<<<(unsigned)((total + 255) / 256), 256>>>(bias);
    }
    // 1) mark S
    mark_s_kernel<<<(BB + 255) / 256, 256>>>(src_ids, dst_ids);
    // 2) build needed-rows list
    build_list_kernel<<<(EE + 255) / 256, 256>>>(eidx);
    // 3) fold projections
    proj_kernel<<<IND, 128>>>(W, a_src, a_dst);
    // 4) s_src/s_dst GEMV
    svec_kernel<<<(NN + 7) / 8, 256>>>(node_emb);
    // 5) relation dots
    rel_dots_kernel<<<(NREL * NH + 7) / 8, 256>>>(rel_feat, a_rel);
    // 6) gather-GEMM for needed h rows
    {
        dim3 grid((HIDD + BN - 1) / BN, (NN + BM - 1) / BM);  // 13 x 391, blocks self-prune
        gemm_rows_kernel<<<grid, 256>>>(node_emb, W);
    }
    // 7) logits + segmax
    edge_logits_kernel<<<(EE * NH + 255) / 256, 256>>>(eidx, etype);
    // 8) exp + denom
    edge_exp_kernel<<<(EE * NH + 255) / 256, 256>>>(eidx);
    // 9) aggregate
    aggregate_kernel<<<(EE + 7) / 8, 256>>>(eidx);
    // 10) DistMult
    distmult_kernel<<<(BB + 7) / 8, 256>>>(rel_emb, src_ids, rel_ids, dst_ids, scores);
}

// round 4
// speedup vs baseline: 3.6210x; 1.7022x over previous
#include <cuda_runtime.h>
#include <cuda_bf16.h>
#include <math.h>
#include <stdint.h>

// ---------------- problem constants ----------------
#define NN    50000
#define IND   1024
#define EE    100000
#define NREL  40
#define NH    4
#define OD    200
#define HIDD  800
#define BB    8192
#define NEG_SLOPE 0.2f

typedef int idx_t;

// ---------------- scratch ----------------
__device__ float g_h[(size_t)NN * HIDD];
__device__ float g_out[(size_t)NN * HIDD];
__device__ __align__(16) __nv_bfloat16 g_Wthi[(size_t)HIDD * IND];  // W^T hi  [n][k]
__device__ __align__(16) __nv_bfloat16 g_Wtlo[(size_t)HIDD * IND];  // W^T lo
__device__ float g_psrc[IND * NH];
__device__ float g_pdst[IND * NH];
__device__ float g_ssrc[NN * NH];
__device__ float g_sdst[NN * NH];
__device__ float g_srel[NREL * NH];
__device__ float g_segmax[NN * NH];
__device__ float g_denom[NN * NH];
__device__ float g_eedge[EE * NH];
__device__ int   g_flagS[NN];
__device__ int   g_needH[NN];
__device__ int   g_rows[NN];
__device__ int   g_cnt;

// ---------------- helpers ----------------
__device__ __forceinline__ void atomicMaxFloat(float* addr, float val) {
    if (val >= 0.0f) atomicMax((int*)addr, __float_as_int(val));
    else atomicMin((unsigned int*)addr, (unsigned int)__float_as_int(val));
}
__device__ __forceinline__ float warpReduceSum(float v) {
    #pragma unroll
    for (int o = 16; o > 0; o >>= 1) v += __shfl_xor_sync(0xFFFFFFFFu, v, o);
    return v;
}
__device__ __forceinline__ void mma_bf16(float* d, const unsigned* a, const unsigned* b) {
    asm("mma.sync.aligned.m16n8k16.row.col.f32.bf16.bf16.f32 "
        "{%0,%1,%2,%3}, {%4,%5,%6,%7}, {%8,%9}, {%0,%1,%2,%3};"
        : "+f"(d[0]), "+f"(d[1]), "+f"(d[2]), "+f"(d[3])
        : "r"(a[0]), "r"(a[1]), "r"(a[2]), "r"(a[3]), "r"(b[0]), "r"(b[1]));
}

// ---------------- 0) reset flags / softmax state ----------------
__global__ void reset_kernel() {
    const int i = blockIdx.x * blockDim.x + threadIdx.x;
    if (i == 0) g_cnt = 0;
    if (i < NN) { g_flagS[i] = 0; g_needH[i] = 0; }
    if (i < NN * NH) { g_segmax[i] = -INFINITY; g_denom[i] = 0.0f; }
}

// ---------------- 1) mark scoring set S ----------------
__global__ void mark_s_kernel(const idx_t* __restrict__ src_ids,
                              const idx_t* __restrict__ dst_ids) {
    const int i = blockIdx.x * blockDim.x + threadIdx.x;
    if (i >= BB) return;
    g_flagS[src_ids[i]] = 1;
    g_flagS[dst_ids[i]] = 1;
}

// ---------------- 2) init g_out = bias, only rows in S ----------------
__global__ __launch_bounds__(128) void init_out_kernel(const float* __restrict__ bias) {
    const int n = blockIdx.x;
    if (!g_flagS[n]) return;
    float* row = g_out + (size_t)n * HIDD;
    for (int c = threadIdx.x; c < HIDD; c += 128) row[c] = bias[c];
}

// ---------------- 3) build list of rows needing h ----------------
__global__ void build_list_kernel(const idx_t* __restrict__ eidx) {
    const int e = blockIdx.x * blockDim.x + threadIdx.x;
    if (e >= EE) return;
    const idx_t dst = eidx[EE + e];
    if (!g_flagS[dst]) return;
    const idx_t src = eidx[e];
    if (atomicExch(&g_needH[src], 1) == 0) {
        const int p = atomicAdd(&g_cnt, 1);
        g_rows[p] = src;
    }
}

// ---------------- 4) fold a_src/a_dst through W ----------------
__global__ __launch_bounds__(128) void proj_kernel(const float* __restrict__ W,
                                                   const float* __restrict__ a_src,
                                                   const float* __restrict__ a_dst) {
    const int k = blockIdx.x;
    const int h = threadIdx.x >> 5;
    const int lane = threadIdx.x & 31;
    float s1 = 0.f, s2 = 0.f;
    for (int d = lane; d < OD; d += 32) {
        const float w = W[(size_t)k * HIDD + h * OD + d];
        s1 = fmaf(w, a_src[h * OD + d], s1);
        s2 = fmaf(w, a_dst[h * OD + d], s2);
    }
    s1 = warpReduceSum(s1);
    s2 = warpReduceSum(s2);
    if (lane == 0) {
        g_psrc[k * NH + h] = s1;
        g_pdst[k * NH + h] = s2;
    }
}

// ---------------- 5) s_src/s_dst GEMV ----------------
__global__ __launch_bounds__(256) void svec_kernel(const float* __restrict__ node_emb) {
    __shared__ float4 ps[IND], pd[IND];
    const int tid = threadIdx.x;
    for (int i = tid; i < IND; i += 256) {
        ps[i] = ((const float4*)g_psrc)[i];
        pd[i] = ((const float4*)g_pdst)[i];
    }
    __syncthreads();
    const int n = blockIdx.x * 8 + (tid >> 5);
    const int lane = tid & 31;
    if (n >= NN) return;
    const float* row = node_emb + (size_t)n * IND;
    float4 s1 = make_float4(0.f, 0.f, 0.f, 0.f);
    float4 s2 = make_float4(0.f, 0.f, 0.f, 0.f);
    #pragma unroll 4
    for (int j = 0; j < IND / 32; j++) {
        const int k = lane + 32 * j;
        const float v = row[k];
        const float4 p1 = ps[k], p2 = pd[k];
        s1.x = fmaf(v, p1.x, s1.x); s1.y = fmaf(v, p1.y, s1.y);
        s1.z = fmaf(v, p1.z, s1.z); s1.w = fmaf(v, p1.w, s1.w);
        s2.x = fmaf(v, p2.x, s2.x); s2.y = fmaf(v, p2.y, s2.y);
        s2.z = fmaf(v, p2.z, s2.z); s2.w = fmaf(v, p2.w, s2.w);
    }
    s1.x = warpReduceSum(s1.x); s1.y = warpReduceSum(s1.y);
    s1.z = warpReduceSum(s1.z); s1.w = warpReduceSum(s1.w);
    s2.x = warpReduceSum(s2.x); s2.y = warpReduceSum(s2.y);
    s2.z = warpReduceSum(s2.z); s2.w = warpReduceSum(s2.w);
    if (lane == 0) {
        ((float4*)g_ssrc)[n] = s1;
        ((float4*)g_sdst)[n] = s2;
    }
}

// ---------------- 6) per-relation dots ----------------
__global__ __launch_bounds__(256) void rel_dots_kernel(const float* __restrict__ rel_feat,
                                                       const float* __restrict__ a_rel) {
    const int gw = blockIdx.x * 8 + (threadIdx.x >> 5);
    const int lane = threadIdx.x & 31;
    if (gw >= NREL * NH) return;
    const int r = gw >> 2, hh = gw & 3;
    float s = 0.f;
    for (int d = lane; d < OD; d += 32)
        s = fmaf(rel_feat[(size_t)r * HIDD + hh * OD + d], a_rel[hh * OD + d], s);
    s = warpReduceSum(s);
    if (lane == 0) g_srel[r * NH + hh] = s;
}

// ---------------- 7) W transpose + split to bf16 hi/lo ----------------
__global__ __launch_bounds__(256) void wconv_kernel(const float* __restrict__ W) {
    __shared__ float t[32][33];
    const int nx = blockIdx.x * 32 + threadIdx.x;
    const int ky = blockIdx.y * 32 + threadIdx.y;
    #pragma unroll
    for (int j = 0; j < 32; j += 8) {
        if (ky + j < IND && nx < HIDD)
            t[threadIdx.y + j][threadIdx.x] = W[(size_t)(ky + j) * HIDD + nx];
    }
    __syncthreads();
    const int ko = blockIdx.y * 32 + threadIdx.x;
    const int no = blockIdx.x * 32 + threadIdx.y;
    #pragma unroll
    for (int j = 0; j < 32; j += 8) {
        if (no + j < HIDD && ko < IND) {
            const float v = t[threadIdx.x][threadIdx.y + j];
            const __nv_bfloat16 hi = __float2bfloat16(v);
            const __nv_bfloat16 lo = __float2bfloat16(v - __bfloat162float(hi));
            g_Wthi[(size_t)(no + j) * IND + ko] = hi;
            g_Wtlo[(size_t)(no + j) * IND + ko] = lo;
        }
    }
}

// ---------------- 8) MMA gather-GEMM: g_h[rows] = node_emb[rows] @ W ----------------
#define BM 128
#define BN 80
#define BK 32
#define SA 40                 // smem row stride in halves
#define AH_OFF 0
#define AL_OFF 5120
#define BH_OFF 10240
#define BL_OFF 13440
#define STAGE_H 16640         // halves per stage
#define GEMM_SMEM (2 * STAGE_H * 2)   // bytes = 66560

__global__ __launch_bounds__(256, 1) void gemm_mma_kernel(const float* __restrict__ A) {
    const int R = *(volatile int*)&g_cnt;
    const int rowBase = blockIdx.y * BM;
    if (rowBase >= R) return;
    const int n0 = blockIdx.x * BN;

    extern __shared__ __nv_bfloat16 sm[];

    const int tid = threadIdx.x;
    const int wid = tid >> 5, lane = tid & 31;
    const int wm = wid & 3, wn = wid >> 2;     // warp tile: 32m x 40n
    const int g = lane >> 2, tg = lane & 3;

    // A gather rows (4 per thread)
    int arows[4];
    const int r0 = tid >> 3;
    #pragma unroll
    for (int i = 0; i < 4; i++) {
        const int lr = rowBase + r0 + i * 32;
        arows[i] = g_rows[lr < NN ? lr : NN - 1];
    }
    const int ac = (tid & 7) * 4;              // k offset (floats) within chunk

    float4 av[4];
    uint4 bvh[2], bvl[2];
    const int br0 = tid >> 2, bc0 = tid & 3;
    const int bi1 = tid + 256;
    const int br1 = bi1 >> 2, bc1 = bi1 & 3;

    auto loadA = [&](int k0) {
        #pragma unroll
        for (int i = 0; i < 4; i++)
            av[i] = *(const float4*)(A + (size_t)arows[i] * IND + k0 + ac);
    };
    auto loadB = [&](int k0) {
        bvh[0] = *((const uint4*)(g_Wthi + (size_t)(n0 + br0) * IND + k0) + bc0);
        bvl[0] = *((const uint4*)(g_Wtlo + (size_t)(n0 + br0) * IND + k0) + bc0);
        if (bi1 < 320) {
            bvh[1] = *((const uint4*)(g_Wthi + (size_t)(n0 + br1) * IND + k0) + bc1);
            bvl[1] = *((const uint4*)(g_Wtlo + (size_t)(n0 + br1) * IND + k0) + bc1);
        }
    };
    auto storeAB = [&](int stage) {
        __nv_bfloat16* base = sm + stage * STAGE_H;
        #pragma unroll
        for (int i = 0; i < 4; i++) {
            const float4 v = av[i];
            const __nv_bfloat16 h0 = __float2bfloat16(v.x);
            const __nv_bfloat16 h1 = __float2bfloat16(v.y);
            const __nv_bfloat16 h2 = __float2bfloat16(v.z);
            const __nv_bfloat16 h3 = __float2bfloat16(v.w);
            const __nv_bfloat16 l0 = __float2bfloat16(v.x - __bfloat162float(h0));
            const __nv_bfloat16 l1 = __float2bfloat16(v.y - __bfloat162float(h1));
            const __nv_bfloat16 l2 = __float2bfloat16(v.z - __bfloat162float(h2));
            const __nv_bfloat16 l3 = __float2bfloat16(v.w - __bfloat162float(h3));
            const int r = r0 + i * 32;
            __nv_bfloat16* pa = base + AH_OFF + r * SA + ac;
            *(__nv_bfloat162*)(pa)     = __halves2bfloat162(h0, h1);
            *(__nv_bfloat162*)(pa + 2) = __halves2bfloat162(h2, h3);
            __nv_bfloat16* pl = base + AL_OFF + r * SA + ac;
            *(__nv_bfloat162*)(pl)     = __halves2bfloat162(l0, l1);
            *(__nv_bfloat162*)(pl + 2) = __halves2bfloat162(l2, l3);
        }
        *(uint4*)(base + BH_OFF + br0 * SA + bc0 * 8) = bvh[0];
        *(uint4*)(base + BL_OFF + br0 * SA + bc0 * 8) = bvl[0];
        if (bi1 < 320) {
            *(uint4*)(base + BH_OFF + br1 * SA + bc1 * 8) = bvh[1];
            *(uint4*)(base + BL_OFF + br1 * SA + bc1 * 8) = bvl[1];
        }
    };

    float acc[2][5][4];
    #pragma unroll
    for (int i = 0; i < 2; i++)
        #pragma unroll
        for (int j = 0; j < 5; j++)
            #pragma unroll
            for (int q = 0; q < 4; q++) acc[i][j][q] = 0.f;

    loadA(0); loadB(0); storeAB(0);

    for (int kc = 0; kc < IND / BK; kc++) {
        __syncthreads();
        if (kc + 1 < IND / BK) { loadA((kc + 1) * BK); loadB((kc + 1) * BK); }

        const __nv_bfloat16* base = sm + (kc & 1) * STAGE_H;
        #pragma unroll
        for (int s = 0; s < 2; s++) {
            unsigned ah[2][4], al[2][4], bh[5][2], bl[5][2];
            #pragma unroll
            for (int i = 0; i < 2; i++) {
                const __nv_bfloat16* p = base + AH_OFF + (wm * 32 + i * 16 + g) * SA + s * 16 + 2 * tg;
                ah[i][0] = *(const unsigned*)(p);
                ah[i][1] = *(const unsigned*)(p + 8 * SA);
                ah[i][2] = *(const unsigned*)(p + 8);
                ah[i][3] = *(const unsigned*)(p + 8 * SA + 8);
                const __nv_bfloat16* q = base + AL_OFF + (wm * 32 + i * 16 + g) * SA + s * 16 + 2 * tg;
                al[i][0] = *(const unsigned*)(q);
                al[i][1] = *(const unsigned*)(q + 8 * SA);
                al[i][2] = *(const unsigned*)(q + 8);
                al[i][3] = *(const unsigned*)(q + 8 * SA + 8);
            }
            #pragma unroll
            for (int j = 0; j < 5; j++) {
                const __nv_bfloat16* p = base + BH_OFF + (wn * 40 + j * 8 + g) * SA + s * 16 + 2 * tg;
                bh[j][0] = *(const unsigned*)(p);
                bh[j][1] = *(const unsigned*)(p + 8);
                const __nv_bfloat16* q = base + BL_OFF + (wn * 40 + j * 8 + g) * SA + s * 16 + 2 * tg;
                bl[j][0] = *(const unsigned*)(q);
                bl[j][1] = *(const unsigned*)(q + 8);
            }
            #pragma unroll
            for (int i = 0; i < 2; i++)
                #pragma unroll
                for (int j = 0; j < 5; j++) mma_bf16(acc[i][j], ah[i], bh[j]);
            #pragma unroll
            for (int i = 0; i < 2; i++)
                #pragma unroll
                for (int j = 0; j < 5; j++) mma_bf16(acc[i][j], ah[i], bl[j]);
            #pragma unroll
            for (int i = 0; i < 2; i++)
                #pragma unroll
                for (int j = 0; j < 5; j++) mma_bf16(acc[i][j], al[i], bh[j]);
        }
        if (kc + 1 < IND / BK) storeAB((kc + 1) & 1);
    }

    // epilogue
    #pragma unroll
    for (int i = 0; i < 2; i++) {
        const int lr0 = rowBase + wm * 32 + i * 16 + g;
        const int lr1 = lr0 + 8;
        #pragma unroll
        for (int j = 0; j < 5; j++) {
            const int col = n0 + wn * 40 + j * 8 + 2 * tg;
            if (lr0 < R)
                *(float2*)(g_h + (size_t)g_rows[lr0] * HIDD + col) = make_float2(acc[i][j][0], acc[i][j][1]);
            if (lr1 < R)
                *(float2*)(g_h + (size_t)g_rows[lr1] * HIDD + col) = make_float2(acc[i][j][2], acc[i][j][3]);
        }
    }
}

// ---------------- 9) edge logits + segment max (filtered) ----------------
__global__ void edge_logits_kernel(const idx_t* __restrict__ eidx,
                                   const idx_t* __restrict__ etype) {
    const int i = blockIdx.x * blockDim.x + threadIdx.x;
    if (i >= EE * NH) return;
    const int e = i >> 2, hh = i & 3;
    const idx_t dst = eidx[EE + e];
    if (!g_flagS[dst]) return;
    const idx_t src = eidx[e];
    const idx_t t = etype[e];
    float l = g_ssrc[src * NH + hh] + g_sdst[dst * NH + hh] + g_srel[t * NH + hh];
    l = (l > 0.0f) ? l : NEG_SLOPE * l;
    g_eedge[i] = l;
    atomicMaxFloat(&g_segmax[dst * NH + hh], l);
}

// ---------------- 10) exp + segment sum (filtered) ----------------
__global__ void edge_exp_kernel(const idx_t* __restrict__ eidx) {
    const int i = blockIdx.x * blockDim.x + threadIdx.x;
    if (i >= EE * NH) return;
    const int e = i >> 2, hh = i & 3;
    const idx_t dst = eidx[EE + e];
    if (!g_flagS[dst]) return;
    const float w = __expf(g_eedge[i] - g_segmax[dst * NH + hh]);
    g_eedge[i] = w;
    atomicAdd(&g_denom[dst * NH + hh], w);
}

// ---------------- 11) weighted scatter-aggregate (filtered) ----------------
__global__ __launch_bounds__(256) void aggregate_kernel(const idx_t* __restrict__ eidx) {
    const int e = blockIdx.x * 8 + (threadIdx.x >> 5);
    const int lane = threadIdx.x & 31;
    if (e >= EE) return;
    const idx_t dst = eidx[EE + e];
    if (!g_flagS[dst]) return;
    const idx_t src = eidx[e];
    const float4* __restrict__ hs = (const float4*)(g_h + (size_t)src * HIDD);
    float* __restrict__ od = g_out + (size_t)dst * HIDD;
    #pragma unroll
    for (int hh = 0; hh < NH; hh++) {
        const float alpha = g_eedge[e * NH + hh] / g_denom[dst * NH + hh];
        const int base = hh * (OD / 4);
        for (int i = lane; i < OD / 4; i += 32) {
            const float4 v = hs[base + i];
            float* p = od + (base + i) * 4;
            atomicAdd(p + 0, alpha * v.x);
            atomicAdd(p + 1, alpha * v.y);
            atomicAdd(p + 2, alpha * v.z);
            atomicAdd(p + 3, alpha * v.w);
        }
    }
}

// ---------------- 12) DistMult scoring ----------------
__global__ __launch_bounds__(256) void distmult_kernel(const float* __restrict__ rel_emb,
                                                       const idx_t* __restrict__ src_ids,
                                                       const idx_t* __restrict__ rel_ids,
                                                       const idx_t* __restrict__ dst_ids,
                                                       float* __restrict__ out) {
    const int b = blockIdx.x * 8 + (threadIdx.x >> 5);
    const int lane = threadIdx.x & 31;
    if (b >= BB) return;
    const idx_t s = src_ids[b];
    const idx_t r = rel_ids[b];
    const idx_t d = dst_ids[b];
    const float4* sv = (const float4*)(g_out + (size_t)s * HIDD);
    const float4* rv = (const float4*)(rel_emb + (size_t)r * HIDD);
    const float4* dv = (const float4*)(g_out + (size_t)d * HIDD);
    float acc = 0.f;
    for (int i = lane; i < HIDD / 4; i += 32) {
        const float4 a = sv[i], bb = rv[i], c = dv[i];
        acc += a.x * bb.x * c.x + a.y * bb.y * c.y + a.z * bb.z * c.z + a.w * bb.w * c.w;
    }
    acc = warpReduceSum(acc);
    if (lane == 0) out[b] = acc;
}

// ---------------- launch ----------------
extern "C" void kernel_launch(void* const* d_in, const int* in_sizes, int n_in,
                              void* d_out, int out_size) {
    const float* node_emb = (const float*)d_in[0];
    const float* W        = (const float*)d_in[1];
    const float* bias     = (const float*)d_in[2];
    const float* a_src    = (const float*)d_in[3];
    const float* a_dst    = (const float*)d_in[4];
    const float* a_rel    = (const float*)d_in[5];
    const float* rel_feat = (const float*)d_in[6];
    const float* rel_emb  = (const float*)d_in[7];
    const idx_t* eidx     = (const idx_t*)d_in[8];
    const idx_t* etype    = (const idx_t*)d_in[9];
    const idx_t* src_ids  = (const idx_t*)d_in[10];
    const idx_t* rel_ids  = (const idx_t*)d_in[11];
    const idx_t* dst_ids  = (const idx_t*)d_in[12];
    float* scores = (float*)d_out;

    reset_kernel<<<(NN * NH + 255) / 256, 256>>>();
    mark_s_kernel<<<(BB + 255) / 256, 256>>>(src_ids, dst_ids);
    init_out_kernel<<<NN, 128>>>(bias);
    build_list_kernel<<<(EE + 255) / 256, 256>>>(eidx);
    proj_kernel<<<IND, 128>>>(W, a_src, a_dst);
    svec_kernel<<<(NN + 7) / 8, 256>>>(node_emb);
    rel_dots_kernel<<<(NREL * NH + 7) / 8, 256>>>(rel_feat, a_rel);
    {
        dim3 grid((HIDD + 31) / 32, (IND + 31) / 32);
        wconv_kernel<<<grid, dim3(32, 8)>>>(W);
    }
    {
        cudaFuncSetAttribute(gemm_mma_kernel, cudaFuncAttributeMaxDynamicSharedMemorySize, GEMM_SMEM);
        dim3 grid(HIDD / BN, (NN + BM - 1) / BM);   // 10 x 391, blocks self-prune on g_cnt
        gemm_mma_kernel<<<grid, 256, GEMM_SMEM>>>(node_emb);
    }
    edge_logits_kernel<<<(EE * NH + 255) / 256, 256>>>(eidx, etype);
    edge_exp_kernel<<<(EE * NH + 255) / 256, 256>>>(eidx);
    aggregate_kernel<<<(EE + 7) / 8, 256>>>(eidx);
    distmult_kernel<<<(BB + 7) / 8, 256>>>(rel_emb, src_ids, rel_ids, dst_ids, scores);
}

// round 5
// speedup vs baseline: 3.9568x; 1.0927x over previous
#include <cuda_runtime.h>
#include <cuda_bf16.h>
#include <math.h>
#include <stdint.h>

// ---------------- problem constants ----------------
#define NN    50000
#define IND   1024
#define EE    100000
#define NREL  40
#define NH    4
#define OD    200
#define HIDD  800
#define BB    8192
#define NEG_SLOPE 0.2f

typedef int idx_t;

// ---------------- scratch ----------------
__device__ float g_h[(size_t)NN * HIDD];
__device__ float g_out[(size_t)NN * HIDD];        // unnormalized aggregate for S rows
__device__ __align__(16) __nv_bfloat16 g_Wthi[(size_t)HIDD * IND];
__device__ __align__(16) __nv_bfloat16 g_Wtlo[(size_t)HIDD * IND];
__device__ float g_psrc[IND * NH];
__device__ float g_pdst[IND * NH];
__device__ __align__(16) float g_ssrc[NN * NH];
__device__ __align__(16) float g_sdst[NN * NH];
__device__ __align__(16) float g_srel[NREL * NH];
__device__ __align__(16) float g_denom[NN * NH];
__device__ int   g_flagS[NN];
__device__ int   g_needH[NN];
__device__ int   g_rows[NN];      // sources of kept edges (need h + s_src)
__device__ int   g_snodes[2 * BB];// scoring-set node list (need s_dst + zero-init)
__device__ int   g_cnt;
__device__ int   g_scnt;

// ---------------- helpers ----------------
__device__ __forceinline__ float warpReduceSum(float v) {
    #pragma unroll
    for (int o = 16; o > 0; o >>= 1) v += __shfl_xor_sync(0xFFFFFFFFu, v, o);
    return v;
}
__device__ __forceinline__ void mma_bf16(float* d, const unsigned* a, const unsigned* b) {
    asm("mma.sync.aligned.m16n8k16.row.col.f32.bf16.bf16.f32 "
        "{%0,%1,%2,%3}, {%4,%5,%6,%7}, {%8,%9}, {%0,%1,%2,%3};"
        : "+f"(d[0]), "+f"(d[1]), "+f"(d[2]), "+f"(d[3])
        : "r"(a[0]), "r"(a[1]), "r"(a[2]), "r"(a[3]), "r"(b[0]), "r"(b[1]));
}
__device__ __forceinline__ void red_add_v4(float* p, float x, float y, float z, float w) {
    asm volatile("red.global.add.v4.f32 [%0], {%1, %2, %3, %4};"
                 :: "l"(p), "f"(x), "f"(y), "f"(z), "f"(w) : "memory");
}

// ---------------- 0) reset ----------------
__global__ void reset_kernel() {
    const int i = blockIdx.x * blockDim.x + threadIdx.x;
    if (i == 0) { g_cnt = 0; g_scnt = 0; }
    if (i < NN) { g_flagS[i] = 0; g_needH[i] = 0; }
    if (i < NN * NH) g_denom[i] = 0.0f;
}

// ---------------- 1) mark scoring set S + build S-list ----------------
__global__ void mark_s_kernel(const idx_t* __restrict__ src_ids,
                              const idx_t* __restrict__ dst_ids) {
    const int i = blockIdx.x * blockDim.x + threadIdx.x;
    if (i >= 2 * BB) return;
    const idx_t n = (i < BB) ? src_ids[i] : dst_ids[i - BB];
    if (atomicExch(&g_flagS[n], 1) == 0) {
        const int p = atomicAdd(&g_scnt, 1);
        g_snodes[p] = n;
    }
}

// ---------------- 2) zero-init g_out for S rows ----------------
__global__ __launch_bounds__(128) void init_out_kernel() {
    const int b = blockIdx.x;
    if (b >= *(volatile int*)&g_scnt) return;
    float4* row = (float4*)(g_out + (size_t)g_snodes[b] * HIDD);
    const float4 z = make_float4(0.f, 0.f, 0.f, 0.f);
    for (int c = threadIdx.x; c < HIDD / 4; c += 128) row[c] = z;
}

// ---------------- 3) build list of rows needing h ----------------
__global__ void build_list_kernel(const idx_t* __restrict__ eidx) {
    const int e = blockIdx.x * blockDim.x + threadIdx.x;
    if (e >= EE) return;
    const idx_t dst = eidx[EE + e];
    if (!g_flagS[dst]) return;
    const idx_t src = eidx[e];
    if (atomicExch(&g_needH[src], 1) == 0) {
        const int p = atomicAdd(&g_cnt, 1);
        g_rows[p] = src;
    }
}

// ---------------- 4) fold a_src/a_dst through W ----------------
__global__ __launch_bounds__(128) void proj_kernel(const float* __restrict__ W,
                                                   const float* __restrict__ a_src,
                                                   const float* __restrict__ a_dst) {
    const int k = blockIdx.x;
    const int h = threadIdx.x >> 5;
    const int lane = threadIdx.x & 31;
    float s1 = 0.f, s2 = 0.f;
    for (int d = lane; d < OD; d += 32) {
        const float w = W[(size_t)k * HIDD + h * OD + d];
        s1 = fmaf(w, a_src[h * OD + d], s1);
        s2 = fmaf(w, a_dst[h * OD + d], s2);
    }
    s1 = warpReduceSum(s1);
    s2 = warpReduceSum(s2);
    if (lane == 0) {
        g_psrc[k * NH + h] = s1;
        g_pdst[k * NH + h] = s2;
    }
}

// ---------------- 5a/5b) list-driven GEMV for s_src / s_dst ----------------
template <bool SRC>
__global__ __launch_bounds__(256) void svec_list_kernel(const float* __restrict__ node_emb) {
    const int cnt = SRC ? *(volatile int*)&g_cnt : *(volatile int*)&g_scnt;
    if (blockIdx.x * 8 >= cnt) return;
    __shared__ float4 ps[IND];
    const int tid = threadIdx.x;
    const float4* pv = (const float4*)(SRC ? g_psrc : g_pdst);
    for (int i = tid; i < IND; i += 256) ps[i] = pv[i];
    __syncthreads();
    const int idx = blockIdx.x * 8 + (tid >> 5);
    const int lane = tid & 31;
    if (idx >= cnt) return;
    const int n = SRC ? g_rows[idx] : g_snodes[idx];
    const float* row = node_emb + (size_t)n * IND;
    float4 s = make_float4(0.f, 0.f, 0.f, 0.f);
    #pragma unroll 4
    for (int j = 0; j < IND / 32; j++) {
        const int k = lane + 32 * j;
        const float v = row[k];
        const float4 p = ps[k];
        s.x = fmaf(v, p.x, s.x); s.y = fmaf(v, p.y, s.y);
        s.z = fmaf(v, p.z, s.z); s.w = fmaf(v, p.w, s.w);
    }
    s.x = warpReduceSum(s.x); s.y = warpReduceSum(s.y);
    s.z = warpReduceSum(s.z); s.w = warpReduceSum(s.w);
    if (lane == 0) {
        if (SRC) ((float4*)g_ssrc)[n] = s;
        else     ((float4*)g_sdst)[n] = s;
    }
}

// ---------------- 6) per-relation dots ----------------
__global__ __launch_bounds__(256) void rel_dots_kernel(const float* __restrict__ rel_feat,
                                                       const float* __restrict__ a_rel) {
    const int gw = blockIdx.x * 8 + (threadIdx.x >> 5);
    const int lane = threadIdx.x & 31;
    if (gw >= NREL * NH) return;
    const int r = gw >> 2, hh = gw & 3;
    float s = 0.f;
    for (int d = lane; d < OD; d += 32)
        s = fmaf(rel_feat[(size_t)r * HIDD + hh * OD + d], a_rel[hh * OD + d], s);
    s = warpReduceSum(s);
    if (lane == 0) g_srel[r * NH + hh] = s;
}

// ---------------- 7) W transpose + split to bf16 hi/lo ----------------
__global__ __launch_bounds__(256) void wconv_kernel(const float* __restrict__ W) {
    __shared__ float t[32][33];
    const int nx = blockIdx.x * 32 + threadIdx.x;
    const int ky = blockIdx.y * 32 + threadIdx.y;
    #pragma unroll
    for (int j = 0; j < 32; j += 8) {
        if (ky + j < IND && nx < HIDD)
            t[threadIdx.y + j][threadIdx.x] = W[(size_t)(ky + j) * HIDD + nx];
    }
    __syncthreads();
    const int ko = blockIdx.y * 32 + threadIdx.x;
    const int no = blockIdx.x * 32 + threadIdx.y;
    #pragma unroll
    for (int j = 0; j < 32; j += 8) {
        if (no + j < HIDD && ko < IND) {
            const float v = t[threadIdx.x][threadIdx.y + j];
            const __nv_bfloat16 hi = __float2bfloat16(v);
            const __nv_bfloat16 lo = __float2bfloat16(v - __bfloat162float(hi));
            g_Wthi[(size_t)(no + j) * IND + ko] = hi;
            g_Wtlo[(size_t)(no + j) * IND + ko] = lo;
        }
    }
}

// ---------------- 8) MMA gather-GEMM ----------------
#define BM 128
#define BN 80
#define BK 32
#define SA 40
#define AH_OFF 0
#define AL_OFF 5120
#define BH_OFF 10240
#define BL_OFF 13440
#define STAGE_H 16640
#define GEMM_SMEM (2 * STAGE_H * 2)

__global__ __launch_bounds__(256, 1) void gemm_mma_kernel(const float* __restrict__ A) {
    const int R = *(volatile int*)&g_cnt;
    const int rowBase = blockIdx.y * BM;
    if (rowBase >= R) return;
    const int n0 = blockIdx.x * BN;

    extern __shared__ __nv_bfloat16 sm[];

    const int tid = threadIdx.x;
    const int wid = tid >> 5, lane = tid & 31;
    const int wm = wid & 3, wn = wid >> 2;
    const int g = lane >> 2, tg = lane & 3;

    int arows[4];
    const int r0 = tid >> 3;
    #pragma unroll
    for (int i = 0; i < 4; i++) {
        const int lr = rowBase + r0 + i * 32;
        arows[i] = g_rows[lr < NN ? lr : NN - 1];
    }
    const int ac = (tid & 7) * 4;

    float4 av[4];
    uint4 bvh[2], bvl[2];
    const int br0 = tid >> 2, bc0 = tid & 3;
    const int bi1 = tid + 256;
    const int br1 = bi1 >> 2, bc1 = bi1 & 3;

    auto loadA = [&](int k0) {
        #pragma unroll
        for (int i = 0; i < 4; i++)
            av[i] = *(const float4*)(A + (size_t)arows[i] * IND + k0 + ac);
    };
    auto loadB = [&](int k0) {
        bvh[0] = *((const uint4*)(g_Wthi + (size_t)(n0 + br0) * IND + k0) + bc0);
        bvl[0] = *((const uint4*)(g_Wtlo + (size_t)(n0 + br0) * IND + k0) + bc0);
        if (bi1 < 320) {
            bvh[1] = *((const uint4*)(g_Wthi + (size_t)(n0 + br1) * IND + k0) + bc1);
            bvl[1] = *((const uint4*)(g_Wtlo + (size_t)(n0 + br1) * IND + k0) + bc1);
        }
    };
    auto storeAB = [&](int stage) {
        __nv_bfloat16* base = sm + stage * STAGE_H;
        #pragma unroll
        for (int i = 0; i < 4; i++) {
            const float4 v = av[i];
            const __nv_bfloat16 h0 = __float2bfloat16(v.x);
            const __nv_bfloat16 h1 = __float2bfloat16(v.y);
            const __nv_bfloat16 h2 = __float2bfloat16(v.z);
            const __nv_bfloat16 h3 = __float2bfloat16(v.w);
            const __nv_bfloat16 l0 = __float2bfloat16(v.x - __bfloat162float(h0));
            const __nv_bfloat16 l1 = __float2bfloat16(v.y - __bfloat162float(h1));
            const __nv_bfloat16 l2 = __float2bfloat16(v.z - __bfloat162float(h2));
            const __nv_bfloat16 l3 = __float2bfloat16(v.w - __bfloat162float(h3));
            const int r = r0 + i * 32;
            __nv_bfloat16* pa = base + AH_OFF + r * SA + ac;
            *(__nv_bfloat162*)(pa)     = __halves2bfloat162(h0, h1);
            *(__nv_bfloat162*)(pa + 2) = __halves2bfloat162(h2, h3);
            __nv_bfloat16* pl = base + AL_OFF + r * SA + ac;
            *(__nv_bfloat162*)(pl)     = __halves2bfloat162(l0, l1);
            *(__nv_bfloat162*)(pl + 2) = __halves2bfloat162(l2, l3);
        }
        *(uint4*)(base + BH_OFF + br0 * SA + bc0 * 8) = bvh[0];
        *(uint4*)(base + BL_OFF + br0 * SA + bc0 * 8) = bvl[0];
        if (bi1 < 320) {
            *(uint4*)(base + BH_OFF + br1 * SA + bc1 * 8) = bvh[1];
            *(uint4*)(base + BL_OFF + br1 * SA + bc1 * 8) = bvl[1];
        }
    };

    float acc[2][5][4];
    #pragma unroll
    for (int i = 0; i < 2; i++)
        #pragma unroll
        for (int j = 0; j < 5; j++)
            #pragma unroll
            for (int q = 0; q < 4; q++) acc[i][j][q] = 0.f;

    loadA(0); loadB(0); storeAB(0);

    for (int kc = 0; kc < IND / BK; kc++) {
        __syncthreads();
        if (kc + 1 < IND / BK) { loadA((kc + 1) * BK); loadB((kc + 1) * BK); }

        const __nv_bfloat16* base = sm + (kc & 1) * STAGE_H;
        #pragma unroll
        for (int s = 0; s < 2; s++) {
            unsigned ah[2][4], al[2][4], bh[5][2], bl[5][2];
            #pragma unroll
            for (int i = 0; i < 2; i++) {
                const __nv_bfloat16* p = base + AH_OFF + (wm * 32 + i * 16 + g) * SA + s * 16 + 2 * tg;
                ah[i][0] = *(const unsigned*)(p);
                ah[i][1] = *(const unsigned*)(p + 8 * SA);
                ah[i][2] = *(const unsigned*)(p + 8);
                ah[i][3] = *(const unsigned*)(p + 8 * SA + 8);
                const __nv_bfloat16* q = base + AL_OFF + (wm * 32 + i * 16 + g) * SA + s * 16 + 2 * tg;
                al[i][0] = *(const unsigned*)(q);
                al[i][1] = *(const unsigned*)(q + 8 * SA);
                al[i][2] = *(const unsigned*)(q + 8);
                al[i][3] = *(const unsigned*)(q + 8 * SA + 8);
            }
            #pragma unroll
            for (int j = 0; j < 5; j++) {
                const __nv_bfloat16* p = base + BH_OFF + (wn * 40 + j * 8 + g) * SA + s * 16 + 2 * tg;
                bh[j][0] = *(const unsigned*)(p);
                bh[j][1] = *(const unsigned*)(p + 8);
                const __nv_bfloat16* q = base + BL_OFF + (wn * 40 + j * 8 + g) * SA + s * 16 + 2 * tg;
                bl[j][0] = *(const unsigned*)(q);
                bl[j][1] = *(const unsigned*)(q + 8);
            }
            #pragma unroll
            for (int i = 0; i < 2; i++)
                #pragma unroll
                for (int j = 0; j < 5; j++) mma_bf16(acc[i][j], ah[i], bh[j]);
            #pragma unroll
            for (int i = 0; i < 2; i++)
                #pragma unroll
                for (int j = 0; j < 5; j++) mma_bf16(acc[i][j], ah[i], bl[j]);
            #pragma unroll
            for (int i = 0; i < 2; i++)
                #pragma unroll
                for (int j = 0; j < 5; j++) mma_bf16(acc[i][j], al[i], bh[j]);
        }
        if (kc + 1 < IND / BK) storeAB((kc + 1) & 1);
    }

    #pragma unroll
    for (int i = 0; i < 2; i++) {
        const int lr0 = rowBase + wm * 32 + i * 16 + g;
        const int lr1 = lr0 + 8;
        #pragma unroll
        for (int j = 0; j < 5; j++) {
            const int col = n0 + wn * 40 + j * 8 + 2 * tg;
            if (lr0 < R)
                *(float2*)(g_h + (size_t)g_rows[lr0] * HIDD + col) = make_float2(acc[i][j][0], acc[i][j][1]);
            if (lr1 < R)
                *(float2*)(g_h + (size_t)g_rows[lr1] * HIDD + col) = make_float2(acc[i][j][2], acc[i][j][3]);
        }
    }
}

// ---------------- 9) fused edge pass: logits -> exp -> denom + unnormalized aggregate ----------------
__global__ __launch_bounds__(256) void edge_all_kernel(const idx_t* __restrict__ eidx,
                                                       const idx_t* __restrict__ etype) {
    const int e = blockIdx.x * 8 + (threadIdx.x >> 5);
    const int lane = threadIdx.x & 31;
    if (e >= EE) return;
    const idx_t dst = eidx[EE + e];
    if (!g_flagS[dst]) return;
    const idx_t src = eidx[e];
    const idx_t t = etype[e];
    const float4 ls = ((const float4*)g_ssrc)[src];
    const float4 ld = ((const float4*)g_sdst)[dst];
    const float4 lr = ((const float4*)g_srel)[t];
    float w[4];
    {
        float l0 = ls.x + ld.x + lr.x; l0 = (l0 > 0.f) ? l0 : NEG_SLOPE * l0;
        float l1 = ls.y + ld.y + lr.y; l1 = (l1 > 0.f) ? l1 : NEG_SLOPE * l1;
        float l2 = ls.z + ld.z + lr.z; l2 = (l2 > 0.f) ? l2 : NEG_SLOPE * l2;
        float l3 = ls.w + ld.w + lr.w; l3 = (l3 > 0.f) ? l3 : NEG_SLOPE * l3;
        w[0] = __expf(l0); w[1] = __expf(l1); w[2] = __expf(l2); w[3] = __expf(l3);
    }
    if (lane < 4) atomicAdd(&g_denom[dst * NH + lane], w[lane]);
    const float4* __restrict__ hs = (const float4*)(g_h + (size_t)src * HIDD);
    float* __restrict__ od = g_out + (size_t)dst * HIDD;
    #pragma unroll
    for (int hh = 0; hh < NH; hh++) {
        const float a = w[hh];
        const int base = hh * (OD / 4);
        #pragma unroll
        for (int i = lane; i < OD / 4; i += 32) {
            const float4 v = hs[base + i];
            red_add_v4(od + (base + i) * 4, a * v.x, a * v.y, a * v.z, a * v.w);
        }
    }
}

// ---------------- 10) DistMult scoring (normalize + bias inline) ----------------
__global__ __launch_bounds__(256) void distmult_kernel(const float* __restrict__ rel_emb,
                                                       const float* __restrict__ bias,
                                                       const idx_t* __restrict__ src_ids,
                                                       const idx_t* __restrict__ rel_ids,
                                                       const idx_t* __restrict__ dst_ids,
                                                       float* __restrict__ out) {
    const int b = blockIdx.x * 8 + (threadIdx.x >> 5);
    const int lane = threadIdx.x & 31;
    if (b >= BB) return;
    const idx_t s = src_ids[b];
    const idx_t r = rel_ids[b];
    const idx_t d = dst_ids[b];
    const float4 dns = ((const float4*)g_denom)[s];
    const float4 dnd = ((const float4*)g_denom)[d];
    float invs[4], invd[4];
    invs[0] = dns.x > 0.f ? 1.f / dns.x : 0.f;
    invs[1] = dns.y > 0.f ? 1.f / dns.y : 0.f;
    invs[2] = dns.z > 0.f ? 1.f / dns.z : 0.f;
    invs[3] = dns.w > 0.f ? 1.f / dns.w : 0.f;
    invd[0] = dnd.x > 0.f ? 1.f / dnd.x : 0.f;
    invd[1] = dnd.y > 0.f ? 1.f / dnd.y : 0.f;
    invd[2] = dnd.z > 0.f ? 1.f / dnd.z : 0.f;
    invd[3] = dnd.w > 0.f ? 1.f / dnd.w : 0.f;
    const float4* sv = (const float4*)(g_out + (size_t)s * HIDD);
    const float4* dv = (const float4*)(g_out + (size_t)d * HIDD);
    const float4* rv = (const float4*)(rel_emb + (size_t)r * HIDD);
    const float4* bv = (const float4*)bias;
    float acc = 0.f;
    #pragma unroll
    for (int hh = 0; hh < NH; hh++) {
        const float is = invs[hh], id = invd[hh];
        const int base = hh * (OD / 4);
        #pragma unroll
        for (int i = lane; i < OD / 4; i += 32) {
            const float4 a = sv[base + i], c = dv[base + i];
            const float4 bb = rv[base + i], bi = bv[base + i];
            const float sx = fmaf(a.x, is, bi.x), dx = fmaf(c.x, id, bi.x);
            const float sy = fmaf(a.y, is, bi.y), dy = fmaf(c.y, id, bi.y);
            const float sz = fmaf(a.z, is, bi.z), dz = fmaf(c.z, id, bi.z);
            const float sw = fmaf(a.w, is, bi.w), dw = fmaf(c.w, id, bi.w);
            acc += sx * bb.x * dx + sy * bb.y * dy + sz * bb.z * dz + sw * bb.w * dw;
        }
    }
    acc = warpReduceSum(acc);
    if (lane == 0) out[b] = acc;
}

// ---------------- launch ----------------
extern "C" void kernel_launch(void* const* d_in, const int* in_sizes, int n_in,
                              void* d_out, int out_size) {
    const float* node_emb = (const float*)d_in[0];
    const float* W        = (const float*)d_in[1];
    const float* bias     = (const float*)d_in[2];
    const float* a_src    = (const float*)d_in[3];
    const float* a_dst    = (const float*)d_in[4];
    const float* a_rel    = (const float*)d_in[5];
    const float* rel_feat = (const float*)d_in[6];
    const float* rel_emb  = (const float*)d_in[7];
    const idx_t* eidx     = (const idx_t*)d_in[8];
    const idx_t* etype    = (const idx_t*)d_in[9];
    const idx_t* src_ids  = (const idx_t*)d_in[10];
    const idx_t* rel_ids  = (const idx_t*)d_in[11];
    const idx_t* dst_ids  = (const idx_t*)d_in[12];
    float* scores = (float*)d_out;

    reset_kernel<<<(NN * NH + 255) / 256, 256>>>();
    mark_s_kernel<<<(2 * BB + 255) / 256, 256>>>(src_ids, dst_ids);
    init_out_kernel<<<2 * BB, 128>>>();
    build_list_kernel<<<(EE + 255) / 256, 256>>>(eidx);
    proj_kernel<<<IND, 128>>>(W, a_src, a_dst);
    svec_list_kernel<true><<<(NN + 7) / 8, 256>>>(node_emb);
    svec_list_kernel<false><<<(2 * BB + 7) / 8, 256>>>(node_emb);
    rel_dots_kernel<<<(NREL * NH + 7) / 8, 256>>>(rel_feat, a_rel);
    {
        dim3 grid((HIDD + 31) / 32, (IND + 31) / 32);
        wconv_kernel<<<grid, dim3(32, 8)>>>(W);
    }
    {
        cudaFuncSetAttribute(gemm_mma_kernel, cudaFuncAttributeMaxDynamicSharedMemorySize, GEMM_SMEM);
        dim3 grid(HIDD / BN, (NN + BM - 1) / BM);
        gemm_mma_kernel<<<grid, 256, GEMM_SMEM>>>(node_emb);
    }
    edge_all_kernel<<<(EE + 7) / 8, 256>>>(eidx, etype);
    distmult_kernel<<<(BB + 7) / 8, 256>>>(rel_emb, bias, src_ids, rel_ids, dst_ids, scores);
}

// round 6
// speedup vs baseline: 5.4742x; 1.3835x over previous
#include <cuda_runtime.h>
#include <cuda_fp16.h>
#include <math.h>
#include <stdint.h>

// ---------------- problem constants ----------------
#define NN    50000
#define IND   1024
#define EE    100000
#define NREL  40
#define NH    4
#define OD    200
#define HIDD  800
#define BB    8192
#define NEG_SLOPE 0.2f

typedef int idx_t;

// ---------------- scratch ----------------
__device__ float g_h[(size_t)NN * HIDD];
__device__ float g_out[(size_t)NN * HIDD];        // unnormalized aggregate for S rows
__device__ __align__(16) __half g_Wth[(size_t)HIDD * IND];   // W^T fp16 [n][k]
__device__ float g_psrc[IND * NH];
__device__ float g_pdst[IND * NH];
__device__ __align__(16) float g_ssrc[NN * NH];
__device__ __align__(16) float g_sdst[NN * NH];
__device__ __align__(16) float g_srel[NREL * NH];
__device__ __align__(16) float g_denom[NN * NH];
__device__ int   g_flagS[NN];
__device__ int   g_needH[NN];
__device__ int   g_rows[NN];        // sources of kept edges (need h + s_src)
__device__ int   g_snodes[2 * BB];  // scoring-set node list
__device__ int   g_elist[EE];       // compacted kept-edge ids
__device__ int   g_cnt;
__device__ int   g_scnt;
__device__ int   g_ecnt;

// ---------------- helpers ----------------
__device__ __forceinline__ float warpReduceSum(float v) {
    #pragma unroll
    for (int o = 16; o > 0; o >>= 1) v += __shfl_xor_sync(0xFFFFFFFFu, v, o);
    return v;
}
__device__ __forceinline__ void mma_fp16(float* d, const unsigned* a, const unsigned* b) {
    asm("mma.sync.aligned.m16n8k16.row.col.f32.f16.f16.f32 "
        "{%0,%1,%2,%3}, {%4,%5,%6,%7}, {%8,%9}, {%0,%1,%2,%3};"
        : "+f"(d[0]), "+f"(d[1]), "+f"(d[2]), "+f"(d[3])
        : "r"(a[0]), "r"(a[1]), "r"(a[2]), "r"(a[3]), "r"(b[0]), "r"(b[1]));
}
__device__ __forceinline__ void red_add_v4(float* p, float x, float y, float z, float w) {
    asm volatile("red.global.add.v4.f32 [%0], {%1, %2, %3, %4};"
                 :: "l"(p), "f"(x), "f"(y), "f"(z), "f"(w) : "memory");
}

// ---------------- 0) reset ----------------
__global__ void reset_kernel() {
    const int i = blockIdx.x * blockDim.x + threadIdx.x;
    if (i == 0) { g_cnt = 0; g_scnt = 0; g_ecnt = 0; }
    if (i < NN) { g_flagS[i] = 0; g_needH[i] = 0; }
    if (i < NN * NH) g_denom[i] = 0.0f;
}

// ---------------- 1) mark scoring set S + build S-list ----------------
__global__ void mark_s_kernel(const idx_t* __restrict__ src_ids,
                              const idx_t* __restrict__ dst_ids) {
    const int i = blockIdx.x * blockDim.x + threadIdx.x;
    if (i >= 2 * BB) return;
    const idx_t n = (i < BB) ? src_ids[i] : dst_ids[i - BB];
    if (atomicExch(&g_flagS[n], 1) == 0) {
        const int p = atomicAdd(&g_scnt, 1);
        g_snodes[p] = n;
    }
}

// ---------------- 2) zero-init g_out for S rows ----------------
__global__ __launch_bounds__(128) void init_out_kernel() {
    const int b = blockIdx.x;
    if (b >= *(volatile int*)&g_scnt) return;
    float4* row = (float4*)(g_out + (size_t)g_snodes[b] * HIDD);
    const float4 z = make_float4(0.f, 0.f, 0.f, 0.f);
    for (int c = threadIdx.x; c < HIDD / 4; c += 128) row[c] = z;
}

// ---------------- 3) build kept-edge list + rows needing h ----------------
__global__ void build_list_kernel(const idx_t* __restrict__ eidx) {
    const int e = blockIdx.x * blockDim.x + threadIdx.x;
    if (e >= EE) return;
    const idx_t dst = eidx[EE + e];
    if (!g_flagS[dst]) return;
    g_elist[atomicAdd(&g_ecnt, 1)] = e;
    const idx_t src = eidx[e];
    if (atomicExch(&g_needH[src], 1) == 0) {
        const int p = atomicAdd(&g_cnt, 1);
        g_rows[p] = src;
    }
}

// ---------------- 4) fold a_src/a_dst through W ----------------
__global__ __launch_bounds__(128) void proj_kernel(const float* __restrict__ W,
                                                   const float* __restrict__ a_src,
                                                   const float* __restrict__ a_dst) {
    const int k = blockIdx.x;
    const int h = threadIdx.x >> 5;
    const int lane = threadIdx.x & 31;
    float s1 = 0.f, s2 = 0.f;
    for (int d = lane; d < OD; d += 32) {
        const float w = W[(size_t)k * HIDD + h * OD + d];
        s1 = fmaf(w, a_src[h * OD + d], s1);
        s2 = fmaf(w, a_dst[h * OD + d], s2);
    }
    s1 = warpReduceSum(s1);
    s2 = warpReduceSum(s2);
    if (lane == 0) {
        g_psrc[k * NH + h] = s1;
        g_pdst[k * NH + h] = s2;
    }
}

// ---------------- 5) list-driven GEMV for s_src / s_dst ----------------
template <bool SRC>
__global__ __launch_bounds__(256) void svec_list_kernel(const float* __restrict__ node_emb) {
    const int cnt = SRC ? *(volatile int*)&g_cnt : *(volatile int*)&g_scnt;
    if (blockIdx.x * 8 >= cnt) return;
    __shared__ float4 ps[IND];
    const int tid = threadIdx.x;
    const float4* pv = (const float4*)(SRC ? g_psrc : g_pdst);
    for (int i = tid; i < IND; i += 256) ps[i] = pv[i];
    __syncthreads();
    const int idx = blockIdx.x * 8 + (tid >> 5);
    const int lane = tid & 31;
    if (idx >= cnt) return;
    const int n = SRC ? g_rows[idx] : g_snodes[idx];
    const float* row = node_emb + (size_t)n * IND;
    float4 s = make_float4(0.f, 0.f, 0.f, 0.f);
    #pragma unroll 4
    for (int j = 0; j < IND / 32; j++) {
        const int k = lane + 32 * j;
        const float v = row[k];
        const float4 p = ps[k];
        s.x = fmaf(v, p.x, s.x); s.y = fmaf(v, p.y, s.y);
        s.z = fmaf(v, p.z, s.z); s.w = fmaf(v, p.w, s.w);
    }
    s.x = warpReduceSum(s.x); s.y = warpReduceSum(s.y);
    s.z = warpReduceSum(s.z); s.w = warpReduceSum(s.w);
    if (lane == 0) {
        if (SRC) ((float4*)g_ssrc)[n] = s;
        else     ((float4*)g_sdst)[n] = s;
    }
}

// ---------------- 6) per-relation dots ----------------
__global__ __launch_bounds__(256) void rel_dots_kernel(const float* __restrict__ rel_feat,
                                                       const float* __restrict__ a_rel) {
    const int gw = blockIdx.x * 8 + (threadIdx.x >> 5);
    const int lane = threadIdx.x & 31;
    if (gw >= NREL * NH) return;
    const int r = gw >> 2, hh = gw & 3;
    float s = 0.f;
    for (int d = lane; d < OD; d += 32)
        s = fmaf(rel_feat[(size_t)r * HIDD + hh * OD + d], a_rel[hh * OD + d], s);
    s = warpReduceSum(s);
    if (lane == 0) g_srel[r * NH + hh] = s;
}

// ---------------- 7) W transpose -> fp16 ----------------
__global__ __launch_bounds__(256) void wconv_kernel(const float* __restrict__ W) {
    __shared__ float t[32][33];
    const int nx = blockIdx.x * 32 + threadIdx.x;
    const int ky = blockIdx.y * 32 + threadIdx.y;
    #pragma unroll
    for (int j = 0; j < 32; j += 8) {
        if (ky + j < IND && nx < HIDD)
            t[threadIdx.y + j][threadIdx.x] = W[(size_t)(ky + j) * HIDD + nx];
    }
    __syncthreads();
    const int ko = blockIdx.y * 32 + threadIdx.x;
    const int no = blockIdx.x * 32 + threadIdx.y;
    #pragma unroll
    for (int j = 0; j < 32; j += 8) {
        if (no + j < HIDD && ko < IND)
            g_Wth[(size_t)(no + j) * IND + ko] = __float2half_rn(t[threadIdx.x][threadIdx.y + j]);
    }
}

// ---------------- 8) MMA gather-GEMM: fp16 A-split 2-pass ----------------
#define BM 128
#define BN 80
#define BK 32
#define SA 40
#define AH_OFF 0
#define AL_OFF 5120
#define BH_OFF 10240
#define STAGE_H 13440
#define GEMM_SMEM (2 * STAGE_H * 2)     // 53760 bytes

__global__ __launch_bounds__(256, 2) void gemm_mma_kernel(const float* __restrict__ A) {
    const int R = *(volatile int*)&g_cnt;
    const int rowBase = blockIdx.y * BM;
    if (rowBase >= R) return;
    const int n0 = blockIdx.x * BN;

    extern __shared__ __half sm[];

    const int tid = threadIdx.x;
    const int wid = tid >> 5, lane = tid & 31;
    const int wm = wid & 3, wn = wid >> 2;
    const int g = lane >> 2, tg = lane & 3;

    int arows[4];
    const int r0 = tid >> 3;
    #pragma unroll
    for (int i = 0; i < 4; i++) {
        const int lr = rowBase + r0 + i * 32;
        arows[i] = g_rows[lr < NN ? lr : NN - 1];
    }
    const int ac = (tid & 7) * 4;

    float4 av[4];
    uint4 bvh[2];
    const int br0 = tid >> 2, bc0 = tid & 3;
    const int bi1 = tid + 256;
    const int br1 = bi1 >> 2, bc1 = bi1 & 3;

    auto loadA = [&](int k0) {
        #pragma unroll
        for (int i = 0; i < 4; i++)
            av[i] = *(const float4*)(A + (size_t)arows[i] * IND + k0 + ac);
    };
    auto loadB = [&](int k0) {
        bvh[0] = *((const uint4*)(g_Wth + (size_t)(n0 + br0) * IND + k0) + bc0);
        if (bi1 < 320)
            bvh[1] = *((const uint4*)(g_Wth + (size_t)(n0 + br1) * IND + k0) + bc1);
    };
    auto storeAB = [&](int stage) {
        __half* base = sm + stage * STAGE_H;
        #pragma unroll
        for (int i = 0; i < 4; i++) {
            const float4 v = av[i];
            const __half h0 = __float2half_rn(v.x);
            const __half h1 = __float2half_rn(v.y);
            const __half h2 = __float2half_rn(v.z);
            const __half h3 = __float2half_rn(v.w);
            const __half l0 = __float2half_rn(v.x - __half2float(h0));
            const __half l1 = __float2half_rn(v.y - __half2float(h1));
            const __half l2 = __float2half_rn(v.z - __half2float(h2));
            const __half l3 = __float2half_rn(v.w - __half2float(h3));
            const int r = r0 + i * 32;
            __half* pa = base + AH_OFF + r * SA + ac;
            *(__half2*)(pa)     = __halves2half2(h0, h1);
            *(__half2*)(pa + 2) = __halves2half2(h2, h3);
            __half* pl = base + AL_OFF + r * SA + ac;
            *(__half2*)(pl)     = __halves2half2(l0, l1);
            *(__half2*)(pl + 2) = __halves2half2(l2, l3);
        }
        *(uint4*)(base + BH_OFF + br0 * SA + bc0 * 8) = bvh[0];
        if (bi1 < 320)
            *(uint4*)(base + BH_OFF + br1 * SA + bc1 * 8) = bvh[1];
    };

    float acc[2][5][4];
    #pragma unroll
    for (int i = 0; i < 2; i++)
        #pragma unroll
        for (int j = 0; j < 5; j++)
            #pragma unroll
            for (int q = 0; q < 4; q++) acc[i][j][q] = 0.f;

    loadA(0); loadB(0); storeAB(0);

    for (int kc = 0; kc < IND / BK; kc++) {
        __syncthreads();
        if (kc + 1 < IND / BK) { loadA((kc + 1) * BK); loadB((kc + 1) * BK); }

        const __half* base = sm + (kc & 1) * STAGE_H;
        #pragma unroll
        for (int s = 0; s < 2; s++) {
            unsigned ah[2][4], al[2][4], bh[5][2];
            #pragma unroll
            for (int i = 0; i < 2; i++) {
                const __half* p = base + AH_OFF + (wm * 32 + i * 16 + g) * SA + s * 16 + 2 * tg;
                ah[i][0] = *(const unsigned*)(p);
                ah[i][1] = *(const unsigned*)(p + 8 * SA);
                ah[i][2] = *(const unsigned*)(p + 8);
                ah[i][3] = *(const unsigned*)(p + 8 * SA + 8);
                const __half* q = base + AL_OFF + (wm * 32 + i * 16 + g) * SA + s * 16 + 2 * tg;
                al[i][0] = *(const unsigned*)(q);
                al[i][1] = *(const unsigned*)(q + 8 * SA);
                al[i][2] = *(const unsigned*)(q + 8);
                al[i][3] = *(const unsigned*)(q + 8 * SA + 8);
            }
            #pragma unroll
            for (int j = 0; j < 5; j++) {
                const __half* p = base + BH_OFF + (wn * 40 + j * 8 + g) * SA + s * 16 + 2 * tg;
                bh[j][0] = *(const unsigned*)(p);
                bh[j][1] = *(const unsigned*)(p + 8);
            }
            #pragma unroll
            for (int i = 0; i < 2; i++)
                #pragma unroll
                for (int j = 0; j < 5; j++) mma_fp16(acc[i][j], ah[i], bh[j]);
            #pragma unroll
            for (int i = 0; i < 2; i++)
                #pragma unroll
                for (int j = 0; j < 5; j++) mma_fp16(acc[i][j], al[i], bh[j]);
        }
        if (kc + 1 < IND / BK) storeAB((kc + 1) & 1);
    }

    #pragma unroll
    for (int i = 0; i < 2; i++) {
        const int lr0 = rowBase + wm * 32 + i * 16 + g;
        const int lr1 = lr0 + 8;
        #pragma unroll
        for (int j = 0; j < 5; j++) {
            const int col = n0 + wn * 40 + j * 8 + 2 * tg;
            if (lr0 < R)
                *(float2*)(g_h + (size_t)g_rows[lr0] * HIDD + col) = make_float2(acc[i][j][0], acc[i][j][1]);
            if (lr1 < R)
                *(float2*)(g_h + (size_t)g_rows[lr1] * HIDD + col) = make_float2(acc[i][j][2], acc[i][j][3]);
        }
    }
}

// ---------------- 9) fused edge pass over compacted list ----------------
__global__ __launch_bounds__(256) void edge_all_kernel(const idx_t* __restrict__ eidx,
                                                       const idx_t* __restrict__ etype) {
    const int ne = *(volatile int*)&g_ecnt;
    const int w = blockIdx.x * 8 + (threadIdx.x >> 5);
    const int lane = threadIdx.x & 31;
    if (w >= ne) return;
    const int e = g_elist[w];
    const idx_t dst = eidx[EE + e];
    const idx_t src = eidx[e];
    const idx_t t = etype[e];
    const float4 ls = ((const float4*)g_ssrc)[src];
    const float4 ld = ((const float4*)g_sdst)[dst];
    const float4 lr = ((const float4*)g_srel)[t];
    float wv[4];
    {
        float l0 = ls.x + ld.x + lr.x; l0 = (l0 > 0.f) ? l0 : NEG_SLOPE * l0;
        float l1 = ls.y + ld.y + lr.y; l1 = (l1 > 0.f) ? l1 : NEG_SLOPE * l1;
        float l2 = ls.z + ld.z + lr.z; l2 = (l2 > 0.f) ? l2 : NEG_SLOPE * l2;
        float l3 = ls.w + ld.w + lr.w; l3 = (l3 > 0.f) ? l3 : NEG_SLOPE * l3;
        wv[0] = __expf(l0); wv[1] = __expf(l1); wv[2] = __expf(l2); wv[3] = __expf(l3);
    }
    if (lane < 4) atomicAdd(&g_denom[dst * NH + lane], wv[lane]);
    const float4* __restrict__ hs = (const float4*)(g_h + (size_t)src * HIDD);
    float* __restrict__ od = g_out + (size_t)dst * HIDD;
    #pragma unroll
    for (int hh = 0; hh < NH; hh++) {
        const float a = wv[hh];
        const int base = hh * (OD / 4);
        #pragma unroll
        for (int i = lane; i < OD / 4; i += 32) {
            const float4 v = hs[base + i];
            red_add_v4(od + (base + i) * 4, a * v.x, a * v.y, a * v.z, a * v.w);
        }
    }
}

// ---------------- 10) DistMult scoring (normalize + bias inline) ----------------
__global__ __launch_bounds__(256) void distmult_kernel(const float* __restrict__ rel_emb,
                                                       const float* __restrict__ bias,
                                                       const idx_t* __restrict__ src_ids,
                                                       const idx_t* __restrict__ rel_ids,
                                                       const idx_t* __restrict__ dst_ids,
                                                       float* __restrict__ out) {
    const int b = blockIdx.x * 8 + (threadIdx.x >> 5);
    const int lane = threadIdx.x & 31;
    if (b >= BB) return;
    const idx_t s = src_ids[b];
    const idx_t r = rel_ids[b];
    const idx_t d = dst_ids[b];
    const float4 dns = ((const float4*)g_denom)[s];
    const float4 dnd = ((const float4*)g_denom)[d];
    float invs[4], invd[4];
    invs[0] = dns.x > 0.f ? 1.f / dns.x : 0.f;
    invs[1] = dns.y > 0.f ? 1.f / dns.y : 0.f;
    invs[2] = dns.z > 0.f ? 1.f / dns.z : 0.f;
    invs[3] = dns.w > 0.f ? 1.f / dns.w : 0.f;
    invd[0] = dnd.x > 0.f ? 1.f / dnd.x : 0.f;
    invd[1] = dnd.y > 0.f ? 1.f / dnd.y : 0.f;
    invd[2] = dnd.z > 0.f ? 1.f / dnd.z : 0.f;
    invd[3] = dnd.w > 0.f ? 1.f / dnd.w : 0.f;
    const float4* sv = (const float4*)(g_out + (size_t)s * HIDD);
    const float4* dv = (const float4*)(g_out + (size_t)d * HIDD);
    const float4* rv = (const float4*)(rel_emb + (size_t)r * HIDD);
    const float4* bv = (const float4*)bias;
    float acc = 0.f;
    #pragma unroll
    for (int hh = 0; hh < NH; hh++) {
        const float is = invs[hh], id = invd[hh];
        const int base = hh * (OD / 4);
        #pragma unroll
        for (int i = lane; i < OD / 4; i += 32) {
            const float4 a = sv[base + i], c = dv[base + i];
            const float4 bb = rv[base + i], bi = bv[base + i];
            const float sx = fmaf(a.x, is, bi.x), dx = fmaf(c.x, id, bi.x);
            const float sy = fmaf(a.y, is, bi.y), dy = fmaf(c.y, id, bi.y);
            const float sz = fmaf(a.z, is, bi.z), dz = fmaf(c.z, id, bi.z);
            const float sw = fmaf(a.w, is, bi.w), dw = fmaf(c.w, id, bi.w);
            acc += sx * bb.x * dx + sy * bb.y * dy + sz * bb.z * dz + sw * bb.w * dw;
        }
    }
    acc = warpReduceSum(acc);
    if (lane == 0) out[b] = acc;
}

// ---------------- launch ----------------
extern "C" void kernel_launch(void* const* d_in, const int* in_sizes, int n_in,
                              void* d_out, int out_size) {
    const float* node_emb = (const float*)d_in[0];
    const float* W        = (const float*)d_in[1];
    const float* bias     = (const float*)d_in[2];
    const float* a_src    = (const float*)d_in[3];
    const float* a_dst    = (const float*)d_in[4];
    const float* a_rel    = (const float*)d_in[5];
    const float* rel_feat = (const float*)d_in[6];
    const float* rel_emb  = (const float*)d_in[7];
    const idx_t* eidx     = (const idx_t*)d_in[8];
    const idx_t* etype    = (const idx_t*)d_in[9];
    const idx_t* src_ids  = (const idx_t*)d_in[10];
    const idx_t* rel_ids  = (const idx_t*)d_in[11];
    const idx_t* dst_ids  = (const idx_t*)d_in[12];
    float* scores = (float*)d_out;

    reset_kernel<<<(NN * NH + 255) / 256, 256>>>();
    mark_s_kernel<<<(2 * BB + 255) / 256, 256>>>(src_ids, dst_ids);
    init_out_kernel<<<2 * BB, 128>>>();
    build_list_kernel<<<(EE + 255) / 256, 256>>>(eidx);
    proj_kernel<<<IND, 128>>>(W, a_src, a_dst);
    svec_list_kernel<true><<<(NN + 7) / 8, 256>>>(node_emb);
    svec_list_kernel<false><<<(2 * BB + 7) / 8, 256>>>(node_emb);
    rel_dots_kernel<<<(NREL * NH + 7) / 8, 256>>>(rel_feat, a_rel);
    {
        dim3 grid((HIDD + 31) / 32, (IND + 31) / 32);
        wconv_kernel<<<grid, dim3(32, 8)>>>(W);
    }
    {
        cudaFuncSetAttribute(gemm_mma_kernel, cudaFuncAttributeMaxDynamicSharedMemorySize, GEMM_SMEM);
        dim3 grid(HIDD / BN, (NN + BM - 1) / BM);
        gemm_mma_kernel<<<grid, 256, GEMM_SMEM>>>(node_emb);
    }
    edge_all_kernel<<<(EE + 7) / 8, 256>>>(eidx, etype);
    distmult_kernel<<<(BB + 7) / 8, 256>>>(rel_emb, bias, src_ids, rel_ids, dst_ids, scores);
}

// round 7
// speedup vs baseline: 6.4991x; 1.1872x over previous
#include <cuda_runtime.h>
#include <cuda_fp16.h>
#include <math.h>
#include <stdint.h>

// ---------------- problem constants ----------------
#define NN    50000
#define IND   1024
#define EE    100000
#define NREL  40
#define NH    4
#define OD    200
#define HIDD  800
#define BB    8192
#define NEG_SLOPE 0.2f

typedef int idx_t;

// ---------------- scratch ----------------
__device__ float g_h[(size_t)NN * HIDD];
__device__ float g_out[(size_t)NN * HIDD];        // unnormalized aggregate for S rows
__device__ __align__(16) __half g_Wth[(size_t)HIDD * IND];   // W^T fp16 [n][k]
__device__ float g_psrc[IND * NH];
__device__ float g_pdst[IND * NH];
__device__ __align__(16) float g_ssrc[NN * NH];
__device__ __align__(16) float g_sdst[NN * NH];
__device__ __align__(16) float g_srel[NREL * NH];
__device__ __align__(16) float g_denom[NN * NH];
__device__ int   g_flagS[NN];
__device__ int   g_needH[NN];
__device__ int   g_rows[NN];        // sources of kept edges (need h + s_src)
__device__ int   g_snodes[2 * BB];  // scoring-set node list
__device__ int   g_elist[EE];       // compacted kept-edge ids
__device__ int   g_cnt;
__device__ int   g_scnt;
__device__ int   g_ecnt;

// ---------------- helpers ----------------
__device__ __forceinline__ float warpReduceSum(float v) {
    #pragma unroll
    for (int o = 16; o > 0; o >>= 1) v += __shfl_xor_sync(0xFFFFFFFFu, v, o);
    return v;
}
__device__ __forceinline__ void mma_fp16(float* d, const unsigned* a, const unsigned* b) {
    asm("mma.sync.aligned.m16n8k16.row.col.f32.f16.f16.f32 "
        "{%0,%1,%2,%3}, {%4,%5,%6,%7}, {%8,%9}, {%0,%1,%2,%3};"
        : "+f"(d[0]), "+f"(d[1]), "+f"(d[2]), "+f"(d[3])
        : "r"(a[0]), "r"(a[1]), "r"(a[2]), "r"(a[3]), "r"(b[0]), "r"(b[1]));
}
__device__ __forceinline__ void red_add_v4(float* p, float x, float y, float z, float w) {
    asm volatile("red.global.add.v4.f32 [%0], {%1, %2, %3, %4};"
                 :: "l"(p), "f"(x), "f"(y), "f"(z), "f"(w) : "memory");
}

// ---------------- 0) reset ----------------
__global__ void reset_kernel() {
    const int i = blockIdx.x * blockDim.x + threadIdx.x;
    if (i == 0) { g_cnt = 0; g_scnt = 0; g_ecnt = 0; }
    if (i < NN) { g_flagS[i] = 0; g_needH[i] = 0; }
    if (i < NN * NH) g_denom[i] = 0.0f;
}

// ---------------- 1) mark scoring set S + build S-list ----------------
__global__ void mark_s_kernel(const idx_t* __restrict__ src_ids,
                              const idx_t* __restrict__ dst_ids) {
    const int i = blockIdx.x * blockDim.x + threadIdx.x;
    if (i >= 2 * BB) return;
    const idx_t n = (i < BB) ? src_ids[i] : dst_ids[i - BB];
    if (atomicExch(&g_flagS[n], 1) == 0) {
        const int p = atomicAdd(&g_scnt, 1);
        g_snodes[p] = n;
    }
}

// ---------------- 2) zero-init g_out for S rows ----------------
__global__ __launch_bounds__(128) void init_out_kernel() {
    const int b = blockIdx.x;
    if (b >= *(volatile int*)&g_scnt) return;
    float4* row = (float4*)(g_out + (size_t)g_snodes[b] * HIDD);
    const float4 z = make_float4(0.f, 0.f, 0.f, 0.f);
    for (int c = threadIdx.x; c < HIDD / 4; c += 128) row[c] = z;
}

// ---------------- 3) build kept-edge list + rows needing h ----------------
__global__ void build_list_kernel(const idx_t* __restrict__ eidx) {
    const int e = blockIdx.x * blockDim.x + threadIdx.x;
    if (e >= EE) return;
    const idx_t dst = eidx[EE + e];
    if (!g_flagS[dst]) return;
    g_elist[atomicAdd(&g_ecnt, 1)] = e;
    const idx_t src = eidx[e];
    if (atomicExch(&g_needH[src], 1) == 0) {
        const int p = atomicAdd(&g_cnt, 1);
        g_rows[p] = src;
    }
}

// ---------------- 4) fold a_src/a_dst through W ----------------
__global__ __launch_bounds__(128) void proj_kernel(const float* __restrict__ W,
                                                   const float* __restrict__ a_src,
                                                   const float* __restrict__ a_dst) {
    const int k = blockIdx.x;
    const int h = threadIdx.x >> 5;
    const int lane = threadIdx.x & 31;
    float s1 = 0.f, s2 = 0.f;
    for (int d = lane; d < OD; d += 32) {
        const float w = W[(size_t)k * HIDD + h * OD + d];
        s1 = fmaf(w, a_src[h * OD + d], s1);
        s2 = fmaf(w, a_dst[h * OD + d], s2);
    }
    s1 = warpReduceSum(s1);
    s2 = warpReduceSum(s2);
    if (lane == 0) {
        g_psrc[k * NH + h] = s1;
        g_pdst[k * NH + h] = s2;
    }
}

// ---------------- 5) list-driven GEMV for s_src / s_dst ----------------
template <bool SRC>
__global__ __launch_bounds__(256) void svec_list_kernel(const float* __restrict__ node_emb) {
    const int cnt = SRC ? *(volatile int*)&g_cnt : *(volatile int*)&g_scnt;
    if (blockIdx.x * 8 >= cnt) return;
    __shared__ float4 ps[IND];
    const int tid = threadIdx.x;
    const float4* pv = (const float4*)(SRC ? g_psrc : g_pdst);
    for (int i = tid; i < IND; i += 256) ps[i] = pv[i];
    __syncthreads();
    const int idx = blockIdx.x * 8 + (tid >> 5);
    const int lane = tid & 31;
    if (idx >= cnt) return;
    const int n = SRC ? g_rows[idx] : g_snodes[idx];
    const float* row = node_emb + (size_t)n * IND;
    float4 s = make_float4(0.f, 0.f, 0.f, 0.f);
    #pragma unroll 4
    for (int j = 0; j < IND / 32; j++) {
        const int k = lane + 32 * j;
        const float v = row[k];
        const float4 p = ps[k];
        s.x = fmaf(v, p.x, s.x); s.y = fmaf(v, p.y, s.y);
        s.z = fmaf(v, p.z, s.z); s.w = fmaf(v, p.w, s.w);
    }
    s.x = warpReduceSum(s.x); s.y = warpReduceSum(s.y);
    s.z = warpReduceSum(s.z); s.w = warpReduceSum(s.w);
    if (lane == 0) {
        if (SRC) ((float4*)g_ssrc)[n] = s;
        else     ((float4*)g_sdst)[n] = s;
    }
}

// ---------------- 6) per-relation dots ----------------
__global__ __launch_bounds__(256) void rel_dots_kernel(const float* __restrict__ rel_feat,
                                                       const float* __restrict__ a_rel) {
    const int gw = blockIdx.x * 8 + (threadIdx.x >> 5);
    const int lane = threadIdx.x & 31;
    if (gw >= NREL * NH) return;
    const int r = gw >> 2, hh = gw & 3;
    float s = 0.f;
    for (int d = lane; d < OD; d += 32)
        s = fmaf(rel_feat[(size_t)r * HIDD + hh * OD + d], a_rel[hh * OD + d], s);
    s = warpReduceSum(s);
    if (lane == 0) g_srel[r * NH + hh] = s;
}

// ---------------- 7) W transpose -> fp16 ----------------
__global__ __launch_bounds__(256) void wconv_kernel(const float* __restrict__ W) {
    __shared__ float t[32][33];
    const int nx = blockIdx.x * 32 + threadIdx.x;
    const int ky = blockIdx.y * 32 + threadIdx.y;
    #pragma unroll
    for (int j = 0; j < 32; j += 8) {
        if (ky + j < IND && nx < HIDD)
            t[threadIdx.y + j][threadIdx.x] = W[(size_t)(ky + j) * HIDD + nx];
    }
    __syncthreads();
    const int ko = blockIdx.y * 32 + threadIdx.x;
    const int no = blockIdx.x * 32 + threadIdx.y;
    #pragma unroll
    for (int j = 0; j < 32; j += 8) {
        if (no + j < HIDD && ko < IND)
            g_Wth[(size_t)(no + j) * IND + ko] = __float2half_rn(t[threadIdx.x][threadIdx.y + j]);
    }
}

// ---------------- 8) MMA gather-GEMM: single-pass fp16 ----------------
#define BM 128
#define BN 80
#define BK 32
#define SA 40
#define AH_OFF 0
#define BH_OFF 5120
#define STAGE_H 8320
#define GEMM_SMEM (2 * STAGE_H * 2)     // 33280 bytes

__global__ __launch_bounds__(256, 2) void gemm_mma_kernel(const float* __restrict__ A) {
    const int R = *(volatile int*)&g_cnt;
    const int rowBase = blockIdx.y * BM;
    if (rowBase >= R) return;
    const int n0 = blockIdx.x * BN;

    extern __shared__ __half sm[];

    const int tid = threadIdx.x;
    const int wid = tid >> 5, lane = tid & 31;
    const int wm = wid & 3, wn = wid >> 2;
    const int g = lane >> 2, tg = lane & 3;

    int arows[4];
    const int r0 = tid >> 3;
    #pragma unroll
    for (int i = 0; i < 4; i++) {
        const int lr = rowBase + r0 + i * 32;
        arows[i] = g_rows[lr < NN ? lr : NN - 1];
    }
    const int ac = (tid & 7) * 4;

    float4 av[4];
    uint4 bvh[2];
    const int br0 = tid >> 2, bc0 = tid & 3;
    const int bi1 = tid + 256;
    const int br1 = bi1 >> 2, bc1 = bi1 & 3;

    auto loadA = [&](int k0) {
        #pragma unroll
        for (int i = 0; i < 4; i++)
            av[i] = *(const float4*)(A + (size_t)arows[i] * IND + k0 + ac);
    };
    auto loadB = [&](int k0) {
        bvh[0] = *((const uint4*)(g_Wth + (size_t)(n0 + br0) * IND + k0) + bc0);
        if (bi1 < 320)
            bvh[1] = *((const uint4*)(g_Wth + (size_t)(n0 + br1) * IND + k0) + bc1);
    };
    auto storeAB = [&](int stage) {
        __half* base = sm + stage * STAGE_H;
        #pragma unroll
        for (int i = 0; i < 4; i++) {
            const float4 v = av[i];
            const __half h0 = __float2half_rn(v.x);
            const __half h1 = __float2half_rn(v.y);
            const __half h2 = __float2half_rn(v.z);
            const __half h3 = __float2half_rn(v.w);
            const int r = r0 + i * 32;
            __half* pa = base + AH_OFF + r * SA + ac;
            *(__half2*)(pa)     = __halves2half2(h0, h1);
            *(__half2*)(pa + 2) = __halves2half2(h2, h3);
        }
        *(uint4*)(base + BH_OFF + br0 * SA + bc0 * 8) = bvh[0];
        if (bi1 < 320)
            *(uint4*)(base + BH_OFF + br1 * SA + bc1 * 8) = bvh[1];
    };

    float acc[2][5][4];
    #pragma unroll
    for (int i = 0; i < 2; i++)
        #pragma unroll
        for (int j = 0; j < 5; j++)
            #pragma unroll
            for (int q = 0; q < 4; q++) acc[i][j][q] = 0.f;

    loadA(0); loadB(0); storeAB(0);

    for (int kc = 0; kc < IND / BK; kc++) {
        __syncthreads();
        if (kc + 1 < IND / BK) { loadA((kc + 1) * BK); loadB((kc + 1) * BK); }

        const __half* base = sm + (kc & 1) * STAGE_H;
        #pragma unroll
        for (int s = 0; s < 2; s++) {
            unsigned ah[2][4], bh[5][2];
            #pragma unroll
            for (int i = 0; i < 2; i++) {
                const __half* p = base + AH_OFF + (wm * 32 + i * 16 + g) * SA + s * 16 + 2 * tg;
                ah[i][0] = *(const unsigned*)(p);
                ah[i][1] = *(const unsigned*)(p + 8 * SA);
                ah[i][2] = *(const unsigned*)(p + 8);
                ah[i][3] = *(const unsigned*)(p + 8 * SA + 8);
            }
            #pragma unroll
            for (int j = 0; j < 5; j++) {
                const __half* p = base + BH_OFF + (wn * 40 + j * 8 + g) * SA + s * 16 + 2 * tg;
                bh[j][0] = *(const unsigned*)(p);
                bh[j][1] = *(const unsigned*)(p + 8);
            }
            #pragma unroll
            for (int i = 0; i < 2; i++)
                #pragma unroll
                for (int j = 0; j < 5; j++) mma_fp16(acc[i][j], ah[i], bh[j]);
        }
        if (kc + 1 < IND / BK) storeAB((kc + 1) & 1);
    }

    #pragma unroll
    for (int i = 0; i < 2; i++) {
        const int lr0 = rowBase + wm * 32 + i * 16 + g;
        const int lr1 = lr0 + 8;
        #pragma unroll
        for (int j = 0; j < 5; j++) {
            const int col = n0 + wn * 40 + j * 8 + 2 * tg;
            if (lr0 < R)
                *(float2*)(g_h + (size_t)g_rows[lr0] * HIDD + col) = make_float2(acc[i][j][0], acc[i][j][1]);
            if (lr1 < R)
                *(float2*)(g_h + (size_t)g_rows[lr1] * HIDD + col) = make_float2(acc[i][j][2], acc[i][j][3]);
        }
    }
}

// ---------------- 9) fused edge pass over compacted list ----------------
__global__ __launch_bounds__(256) void edge_all_kernel(const idx_t* __restrict__ eidx,
                                                       const idx_t* __restrict__ etype) {
    const int ne = *(volatile int*)&g_ecnt;
    const int w = blockIdx.x * 8 + (threadIdx.x >> 5);
    const int lane = threadIdx.x & 31;
    if (w >= ne) return;
    const int e = g_elist[w];
    const idx_t dst = eidx[EE + e];
    const idx_t src = eidx[e];
    const idx_t t = etype[e];
    const float4 ls = ((const float4*)g_ssrc)[src];
    const float4 ld = ((const float4*)g_sdst)[dst];
    const float4 lr = ((const float4*)g_srel)[t];
    float wv[4];
    {
        float l0 = ls.x + ld.x + lr.x; l0 = (l0 > 0.f) ? l0 : NEG_SLOPE * l0;
        float l1 = ls.y + ld.y + lr.y; l1 = (l1 > 0.f) ? l1 : NEG_SLOPE * l1;
        float l2 = ls.z + ld.z + lr.z; l2 = (l2 > 0.f) ? l2 : NEG_SLOPE * l2;
        float l3 = ls.w + ld.w + lr.w; l3 = (l3 > 0.f) ? l3 : NEG_SLOPE * l3;
        wv[0] = __expf(l0); wv[1] = __expf(l1); wv[2] = __expf(l2); wv[3] = __expf(l3);
    }
    if (lane < 4) atomicAdd(&g_denom[dst * NH + lane], wv[lane]);
    const float4* __restrict__ hs = (const float4*)(g_h + (size_t)src * HIDD);
    float* __restrict__ od = g_out + (size_t)dst * HIDD;
    #pragma unroll
    for (int hh = 0; hh < NH; hh++) {
        const float a = wv[hh];
        const int base = hh * (OD / 4);
        #pragma unroll
        for (int i = lane; i < OD / 4; i += 32) {
            const float4 v = hs[base + i];
            red_add_v4(od + (base + i) * 4, a * v.x, a * v.y, a * v.z, a * v.w);
        }
    }
}

// ---------------- 10) DistMult scoring (normalize + bias inline) ----------------
__global__ __launch_bounds__(256) void distmult_kernel(const float* __restrict__ rel_emb,
                                                       const float* __restrict__ bias,
                                                       const idx_t* __restrict__ src_ids,
                                                       const idx_t* __restrict__ rel_ids,
                                                       const idx_t* __restrict__ dst_ids,
                                                       float* __restrict__ out) {
    const int b = blockIdx.x * 8 + (threadIdx.x >> 5);
    const int lane = threadIdx.x & 31;
    if (b >= BB) return;
    const idx_t s = src_ids[b];
    const idx_t r = rel_ids[b];
    const idx_t d = dst_ids[b];
    const float4 dns = ((const float4*)g_denom)[s];
    const float4 dnd = ((const float4*)g_denom)[d];
    float invs[4], invd[4];
    invs[0] = dns.x > 0.f ? 1.f / dns.x : 0.f;
    invs[1] = dns.y > 0.f ? 1.f / dns.y : 0.f;
    invs[2] = dns.z > 0.f ? 1.f / dns.z : 0.f;
    invs[3] = dns.w > 0.f ? 1.f / dns.w : 0.f;
    invd[0] = dnd.x > 0.f ? 1.f / dnd.x : 0.f;
    invd[1] = dnd.y > 0.f ? 1.f / dnd.y : 0.f;
    invd[2] = dnd.z > 0.f ? 1.f / dnd.z : 0.f;
    invd[3] = dnd.w > 0.f ? 1.f / dnd.w : 0.f;
    const float4* sv = (const float4*)(g_out + (size_t)s * HIDD);
    const float4* dv = (const float4*)(g_out + (size_t)d * HIDD);
    const float4* rv = (const float4*)(rel_emb + (size_t)r * HIDD);
    const float4* bv = (const float4*)bias;
    float acc = 0.f;
    #pragma unroll
    for (int hh = 0; hh < NH; hh++) {
        const float is = invs[hh], id = invd[hh];
        const int base = hh * (OD / 4);
        #pragma unroll
        for (int i = lane; i < OD / 4; i += 32) {
            const float4 a = sv[base + i], c = dv[base + i];
            const float4 bb = rv[base + i], bi = bv[base + i];
            const float sx = fmaf(a.x, is, bi.x), dx = fmaf(c.x, id, bi.x);
            const float sy = fmaf(a.y, is, bi.y), dy = fmaf(c.y, id, bi.y);
            const float sz = fmaf(a.z, is, bi.z), dz = fmaf(c.z, id, bi.z);
            const float sw = fmaf(a.w, is, bi.w), dw = fmaf(c.w, id, bi.w);
            acc += sx * bb.x * dx + sy * bb.y * dy + sz * bb.z * dz + sw * bb.w * dw;
        }
    }
    acc = warpReduceSum(acc);
    if (lane == 0) out[b] = acc;
}

// ---------------- launch ----------------
extern "C" void kernel_launch(void* const* d_in, const int* in_sizes, int n_in,
                              void* d_out, int out_size) {
    const float* node_emb = (const float*)d_in[0];
    const float* W        = (const float*)d_in[1];
    const float* bias     = (const float*)d_in[2];
    const float* a_src    = (const float*)d_in[3];
    const float* a_dst    = (const float*)d_in[4];
    const float* a_rel    = (const float*)d_in[5];
    const float* rel_feat = (const float*)d_in[6];
    const float* rel_emb  = (const float*)d_in[7];
    const idx_t* eidx     = (const idx_t*)d_in[8];
    const idx_t* etype    = (const idx_t*)d_in[9];
    const idx_t* src_ids  = (const idx_t*)d_in[10];
    const idx_t* rel_ids  = (const idx_t*)d_in[11];
    const idx_t* dst_ids  = (const idx_t*)d_in[12];
    float* scores = (float*)d_out;

    reset_kernel<<<(NN * NH + 255) / 256, 256>>>();
    mark_s_kernel<<<(2 * BB + 255) / 256, 256>>>(src_ids, dst_ids);
    init_out_kernel<<<2 * BB, 128>>>();
    build_list_kernel<<<(EE + 255) / 256, 256>>>(eidx);
    proj_kernel<<<IND, 128>>>(W, a_src, a_dst);
    svec_list_kernel<true><<<(NN + 7) / 8, 256>>>(node_emb);
    svec_list_kernel<false><<<(2 * BB + 7) / 8, 256>>>(node_emb);
    rel_dots_kernel<<<(NREL * NH + 7) / 8, 256>>>(rel_feat, a_rel);
    {
        dim3 grid((HIDD + 31) / 32, (IND + 31) / 32);
        wconv_kernel<<<grid, dim3(32, 8)>>>(W);
    }
    {
        cudaFuncSetAttribute(gemm_mma_kernel, cudaFuncAttributeMaxDynamicSharedMemorySize, GEMM_SMEM);
        dim3 grid(HIDD / BN, (NN + BM - 1) / BM);
        gemm_mma_kernel<<<grid, 256, GEMM_SMEM>>>(node_emb);
    }
    edge_all_kernel<<<(EE + 7) / 8, 256>>>(eidx, etype);
    distmult_kernel<<<(BB + 7) / 8, 256>>>(rel_emb, bias, src_ids, rel_ids, dst_ids, scores);
}

// round 8
// speedup vs baseline: 6.5118x; 1.0020x over previous
#include <cuda_runtime.h>
#include <cuda_fp16.h>
#include <math.h>
#include <stdint.h>

// ---------------- problem constants ----------------
#define NN    50000
#define IND   1024
#define EE    100000
#define NREL  40
#define NH    4
#define OD    200
#define HIDD  800
#define BB    8192
#define NEG_SLOPE 0.2f

typedef int idx_t;

// ---------------- scratch ----------------
__device__ float g_h[(size_t)NN * HIDD];
__device__ float g_out[(size_t)NN * HIDD];        // unnormalized aggregate for S rows
__device__ __align__(16) __half g_Wth[(size_t)HIDD * IND];   // W^T fp16 [n][k]
__device__ float g_psrc[IND * NH];
__device__ float g_pdst[IND * NH];
__device__ __align__(16) float g_ssrc[NN * NH];
__device__ __align__(16) float g_sdst[NN * NH];
__device__ __align__(16) float g_srel[NREL * NH];
__device__ __align__(16) float g_denom[NN * NH];
__device__ int   g_flagS[NN];
__device__ int   g_needH[NN];
__device__ int   g_rows[NN];        // sources of kept edges (need h + s_src)
__device__ int   g_snodes[2 * BB];  // scoring-set node list
__device__ int   g_elist[EE];       // compacted kept-edge ids
__device__ int   g_cnt;
__device__ int   g_scnt;
__device__ int   g_ecnt;

// ---------------- helpers ----------------
__device__ __forceinline__ float warpReduceSum(float v) {
    #pragma unroll
    for (int o = 16; o > 0; o >>= 1) v += __shfl_xor_sync(0xFFFFFFFFu, v, o);
    return v;
}
__device__ __forceinline__ void mma_fp16(float* d, const unsigned* a, const unsigned* b) {
    asm("mma.sync.aligned.m16n8k16.row.col.f32.f16.f16.f32 "
        "{%0,%1,%2,%3}, {%4,%5,%6,%7}, {%8,%9}, {%0,%1,%2,%3};"
        : "+f"(d[0]), "+f"(d[1]), "+f"(d[2]), "+f"(d[3])
        : "r"(a[0]), "r"(a[1]), "r"(a[2]), "r"(a[3]), "r"(b[0]), "r"(b[1]));
}
__device__ __forceinline__ void red_add_v4(float* p, float x, float y, float z, float w) {
    asm volatile("red.global.add.v4.f32 [%0], {%1, %2, %3, %4};"
                 :: "l"(p), "f"(x), "f"(y), "f"(z), "f"(w) : "memory");
}

// ---------------- 0) reset ----------------
__global__ void reset_kernel() {
    const int i = blockIdx.x * blockDim.x + threadIdx.x;
    if (i == 0) { g_cnt = 0; g_scnt = 0; g_ecnt = 0; }
    if (i < NN) { g_flagS[i] = 0; g_needH[i] = 0; }
    if (i < NN * NH) g_denom[i] = 0.0f;
}

// ---------------- 1) mark scoring set S + build S-list ----------------
__global__ void mark_s_kernel(const idx_t* __restrict__ src_ids,
                              const idx_t* __restrict__ dst_ids) {
    const int i = blockIdx.x * blockDim.x + threadIdx.x;
    if (i >= 2 * BB) return;
    const idx_t n = (i < BB) ? src_ids[i] : dst_ids[i - BB];
    if (atomicExch(&g_flagS[n], 1) == 0) {
        const int p = atomicAdd(&g_scnt, 1);
        g_snodes[p] = n;
    }
}

// ---------------- 2) zero-init g_out for S rows ----------------
__global__ __launch_bounds__(128) void init_out_kernel() {
    const int b = blockIdx.x;
    if (b >= *(volatile int*)&g_scnt) return;
    float4* row = (float4*)(g_out + (size_t)g_snodes[b] * HIDD);
    const float4 z = make_float4(0.f, 0.f, 0.f, 0.f);
    for (int c = threadIdx.x; c < HIDD / 4; c += 128) row[c] = z;
}

// ---------------- 3) build kept-edge list + rows needing h ----------------
__global__ void build_list_kernel(const idx_t* __restrict__ eidx) {
    const int e = blockIdx.x * blockDim.x + threadIdx.x;
    if (e >= EE) return;
    const idx_t dst = eidx[EE + e];
    if (!g_flagS[dst]) return;
    g_elist[atomicAdd(&g_ecnt, 1)] = e;
    const idx_t src = eidx[e];
    if (atomicExch(&g_needH[src], 1) == 0) {
        const int p = atomicAdd(&g_cnt, 1);
        g_rows[p] = src;
    }
}

// ---------------- 4) fold a_src/a_dst through W ----------------
__global__ __launch_bounds__(128) void proj_kernel(const float* __restrict__ W,
                                                   const float* __restrict__ a_src,
                                                   const float* __restrict__ a_dst) {
    const int k = blockIdx.x;
    const int h = threadIdx.x >> 5;
    const int lane = threadIdx.x & 31;
    float s1 = 0.f, s2 = 0.f;
    for (int d = lane; d < OD; d += 32) {
        const float w = W[(size_t)k * HIDD + h * OD + d];
        s1 = fmaf(w, a_src[h * OD + d], s1);
        s2 = fmaf(w, a_dst[h * OD + d], s2);
    }
    s1 = warpReduceSum(s1);
    s2 = warpReduceSum(s2);
    if (lane == 0) {
        g_psrc[k * NH + h] = s1;
        g_pdst[k * NH + h] = s2;
    }
}

// ---------------- 5) list-driven GEMV for s_src / s_dst ----------------
template <bool SRC>
__global__ __launch_bounds__(256) void svec_list_kernel(const float* __restrict__ node_emb) {
    const int cnt = SRC ? *(volatile int*)&g_cnt : *(volatile int*)&g_scnt;
    if (blockIdx.x * 8 >= cnt) return;
    __shared__ float4 ps[IND];
    const int tid = threadIdx.x;
    const float4* pv = (const float4*)(SRC ? g_psrc : g_pdst);
    for (int i = tid; i < IND; i += 256) ps[i] = pv[i];
    __syncthreads();
    const int idx = blockIdx.x * 8 + (tid >> 5);
    const int lane = tid & 31;
    if (idx >= cnt) return;
    const int n = SRC ? g_rows[idx] : g_snodes[idx];
    const float* row = node_emb + (size_t)n * IND;
    float4 s = make_float4(0.f, 0.f, 0.f, 0.f);
    #pragma unroll 4
    for (int j = 0; j < IND / 32; j++) {
        const int k = lane + 32 * j;
        const float v = row[k];
        const float4 p = ps[k];
        s.x = fmaf(v, p.x, s.x); s.y = fmaf(v, p.y, s.y);
        s.z = fmaf(v, p.z, s.z); s.w = fmaf(v, p.w, s.w);
    }
    s.x = warpReduceSum(s.x); s.y = warpReduceSum(s.y);
    s.z = warpReduceSum(s.z); s.w = warpReduceSum(s.w);
    if (lane == 0) {
        if (SRC) ((float4*)g_ssrc)[n] = s;
        else     ((float4*)g_sdst)[n] = s;
    }
}

// ---------------- 6) per-relation dots ----------------
__global__ __launch_bounds__(256) void rel_dots_kernel(const float* __restrict__ rel_feat,
                                                       const float* __restrict__ a_rel) {
    const int gw = blockIdx.x * 8 + (threadIdx.x >> 5);
    const int lane = threadIdx.x & 31;
    if (gw >= NREL * NH) return;
    const int r = gw >> 2, hh = gw & 3;
    float s = 0.f;
    for (int d = lane; d < OD; d += 32)
        s = fmaf(rel_feat[(size_t)r * HIDD + hh * OD + d], a_rel[hh * OD + d], s);
    s = warpReduceSum(s);
    if (lane == 0) g_srel[r * NH + hh] = s;
}

// ---------------- 7) W transpose -> fp16 ----------------
__global__ __launch_bounds__(256) void wconv_kernel(const float* __restrict__ W) {
    __shared__ float t[32][33];
    const int nx = blockIdx.x * 32 + threadIdx.x;
    const int ky = blockIdx.y * 32 + threadIdx.y;
    #pragma unroll
    for (int j = 0; j < 32; j += 8) {
        if (ky + j < IND && nx < HIDD)
            t[threadIdx.y + j][threadIdx.x] = W[(size_t)(ky + j) * HIDD + nx];
    }
    __syncthreads();
    const int ko = blockIdx.y * 32 + threadIdx.x;
    const int no = blockIdx.x * 32 + threadIdx.y;
    #pragma unroll
    for (int j = 0; j < 32; j += 8) {
        if (no + j < HIDD && ko < IND)
            g_Wth[(size_t)(no + j) * IND + ko] = __float2half_rn(t[threadIdx.x][threadIdx.y + j]);
    }
}

// ---------------- 8) MMA gather-GEMM: single-pass fp16 ----------------
#define BM 128
#define BN 80
#define BK 32
#define SA 40
#define AH_OFF 0
#define BH_OFF 5120
#define STAGE_H 8320
#define GEMM_SMEM (2 * STAGE_H * 2)     // 33280 bytes

__global__ __launch_bounds__(256, 2) void gemm_mma_kernel(const float* __restrict__ A) {
    const int R = *(volatile int*)&g_cnt;
    const int rowBase = blockIdx.y * BM;
    if (rowBase >= R) return;
    const int n0 = blockIdx.x * BN;

    extern __shared__ __half sm[];

    const int tid = threadIdx.x;
    const int wid = tid >> 5, lane = tid & 31;
    const int wm = wid & 3, wn = wid >> 2;
    const int g = lane >> 2, tg = lane & 3;

    int arows[4];
    const int r0 = tid >> 3;
    #pragma unroll
    for (int i = 0; i < 4; i++) {
        const int lr = rowBase + r0 + i * 32;
        arows[i] = g_rows[lr < NN ? lr : NN - 1];
    }
    const int ac = (tid & 7) * 4;

    float4 av[4];
    uint4 bvh[2];
    const int br0 = tid >> 2, bc0 = tid & 3;
    const int bi1 = tid + 256;
    const int br1 = bi1 >> 2, bc1 = bi1 & 3;

    auto loadA = [&](int k0) {
        #pragma unroll
        for (int i = 0; i < 4; i++)
            av[i] = *(const float4*)(A + (size_t)arows[i] * IND + k0 + ac);
    };
    auto loadB = [&](int k0) {
        bvh[0] = *((const uint4*)(g_Wth + (size_t)(n0 + br0) * IND + k0) + bc0);
        if (bi1 < 320)
            bvh[1] = *((const uint4*)(g_Wth + (size_t)(n0 + br1) * IND + k0) + bc1);
    };
    auto storeAB = [&](int stage) {
        __half* base = sm + stage * STAGE_H;
        #pragma unroll
        for (int i = 0; i < 4; i++) {
            const float4 v = av[i];
            const __half h0 = __float2half_rn(v.x);
            const __half h1 = __float2half_rn(v.y);
            const __half h2 = __float2half_rn(v.z);
            const __half h3 = __float2half_rn(v.w);
            const int r = r0 + i * 32;
            __half* pa = base + AH_OFF + r * SA + ac;
            *(__half2*)(pa)     = __halves2half2(h0, h1);
            *(__half2*)(pa + 2) = __halves2half2(h2, h3);
        }
        *(uint4*)(base + BH_OFF + br0 * SA + bc0 * 8) = bvh[0];
        if (bi1 < 320)
            *(uint4*)(base + BH_OFF + br1 * SA + bc1 * 8) = bvh[1];
    };

    float acc[2][5][4];
    #pragma unroll
    for (int i = 0; i < 2; i++)
        #pragma unroll
        for (int j = 0; j < 5; j++)
            #pragma unroll
            for (int q = 0; q < 4; q++) acc[i][j][q] = 0.f;

    loadA(0); loadB(0); storeAB(0);

    for (int kc = 0; kc < IND / BK; kc++) {
        __syncthreads();
        if (kc + 1 < IND / BK) { loadA((kc + 1) * BK); loadB((kc + 1) * BK); }

        const __half* base = sm + (kc & 1) * STAGE_H;
        #pragma unroll
        for (int s = 0; s < 2; s++) {
            unsigned ah[2][4], bh[5][2];
            #pragma unroll
            for (int i = 0; i < 2; i++) {
                const __half* p = base + AH_OFF + (wm * 32 + i * 16 + g) * SA + s * 16 + 2 * tg;
                ah[i][0] = *(const unsigned*)(p);
                ah[i][1] = *(const unsigned*)(p + 8 * SA);
                ah[i][2] = *(const unsigned*)(p + 8);
                ah[i][3] = *(const unsigned*)(p + 8 * SA + 8);
            }
            #pragma unroll
            for (int j = 0; j < 5; j++) {
                const __half* p = base + BH_OFF + (wn * 40 + j * 8 + g) * SA + s * 16 + 2 * tg;
                bh[j][0] = *(const unsigned*)(p);
                bh[j][1] = *(const unsigned*)(p + 8);
            }
            #pragma unroll
            for (int i = 0; i < 2; i++)
                #pragma unroll
                for (int j = 0; j < 5; j++) mma_fp16(acc[i][j], ah[i], bh[j]);
        }
        if (kc + 1 < IND / BK) storeAB((kc + 1) & 1);
    }

    #pragma unroll
    for (int i = 0; i < 2; i++) {
        const int lr0 = rowBase + wm * 32 + i * 16 + g;
        const int lr1 = lr0 + 8;
        #pragma unroll
        for (int j = 0; j < 5; j++) {
            const int col = n0 + wn * 40 + j * 8 + 2 * tg;
            if (lr0 < R)
                *(float2*)(g_h + (size_t)g_rows[lr0] * HIDD + col) = make_float2(acc[i][j][0], acc[i][j][1]);
            if (lr1 < R)
                *(float2*)(g_h + (size_t)g_rows[lr1] * HIDD + col) = make_float2(acc[i][j][2], acc[i][j][3]);
        }
    }
}

// ---------------- 9) fused edge pass over compacted list ----------------
__global__ __launch_bounds__(256) void edge_all_kernel(const idx_t* __restrict__ eidx,
                                                       const idx_t* __restrict__ etype) {
    const int ne = *(volatile int*)&g_ecnt;
    const int w = blockIdx.x * 8 + (threadIdx.x >> 5);
    const int lane = threadIdx.x & 31;
    if (w >= ne) return;
    const int e = g_elist[w];
    const idx_t dst = eidx[EE + e];
    const idx_t src = eidx[e];
    const idx_t t = etype[e];
    const float4 ls = ((const float4*)g_ssrc)[src];
    const float4 ld = ((const float4*)g_sdst)[dst];
    const float4 lr = ((const float4*)g_srel)[t];
    float wv[4];
    {
        float l0 = ls.x + ld.x + lr.x; l0 = (l0 > 0.f) ? l0 : NEG_SLOPE * l0;
        float l1 = ls.y + ld.y + lr.y; l1 = (l1 > 0.f) ? l1 : NEG_SLOPE * l1;
        float l2 = ls.z + ld.z + lr.z; l2 = (l2 > 0.f) ? l2 : NEG_SLOPE * l2;
        float l3 = ls.w + ld.w + lr.w; l3 = (l3 > 0.f) ? l3 : NEG_SLOPE * l3;
        wv[0] = __expf(l0); wv[1] = __expf(l1); wv[2] = __expf(l2); wv[3] = __expf(l3);
    }
    if (lane < 4) atomicAdd(&g_denom[dst * NH + lane], wv[lane]);
    const float4* __restrict__ hs = (const float4*)(g_h + (size_t)src * HIDD);
    float* __restrict__ od = g_out + (size_t)dst * HIDD;
    #pragma unroll
    for (int hh = 0; hh < NH; hh++) {
        const float a = wv[hh];
        const int base = hh * (OD / 4);
        #pragma unroll
        for (int i = lane; i < OD / 4; i += 32) {
            const float4 v = hs[base + i];
            red_add_v4(od + (base + i) * 4, a * v.x, a * v.y, a * v.z, a * v.w);
        }
    }
}

// ---------------- 10) DistMult scoring (normalize + bias inline) ----------------
__global__ __launch_bounds__(256) void distmult_kernel(const float* __restrict__ rel_emb,
                                                       const float* __restrict__ bias,
                                                       const idx_t* __restrict__ src_ids,
                                                       const idx_t* __restrict__ rel_ids,
                                                       const idx_t* __restrict__ dst_ids,
                                                       float* __restrict__ out) {
    const int b = blockIdx.x * 8 + (threadIdx.x >> 5);
    const int lane = threadIdx.x & 31;
    if (b >= BB) return;
    const idx_t s = src_ids[b];
    const idx_t r = rel_ids[b];
    const idx_t d = dst_ids[b];
    const float4 dns = ((const float4*)g_denom)[s];
    const float4 dnd = ((const float4*)g_denom)[d];
    float invs[4], invd[4];
    invs[0] = dns.x > 0.f ? 1.f / dns.x : 0.f;
    invs[1] = dns.y > 0.f ? 1.f / dns.y : 0.f;
    invs[2] = dns.z > 0.f ? 1.f / dns.z : 0.f;
    invs[3] = dns.w > 0.f ? 1.f / dns.w : 0.f;
    invd[0] = dnd.x > 0.f ? 1.f / dnd.x : 0.f;
    invd[1] = dnd.y > 0.f ? 1.f / dnd.y : 0.f;
    invd[2] = dnd.z > 0.f ? 1.f / dnd.z : 0.f;
    invd[3] = dnd.w > 0.f ? 1.f / dnd.w : 0.f;
    const float4* sv = (const float4*)(g_out + (size_t)s * HIDD);
    const float4* dv = (const float4*)(g_out + (size_t)d * HIDD);
    const float4* rv = (const float4*)(rel_emb + (size_t)r * HIDD);
    const float4* bv = (const float4*)bias;
    float acc = 0.f;
    #pragma unroll
    for (int hh = 0; hh < NH; hh++) {
        const float is = invs[hh], id = invd[hh];
        const int base = hh * (OD / 4);
        #pragma unroll
        for (int i = lane; i < OD / 4; i += 32) {
            const float4 a = sv[base + i], c = dv[base + i];
            const float4 bb = rv[base + i], bi = bv[base + i];
            const float sx = fmaf(a.x, is, bi.x), dx = fmaf(c.x, id, bi.x);
            const float sy = fmaf(a.y, is, bi.y), dy = fmaf(c.y, id, bi.y);
            const float sz = fmaf(a.z, is, bi.z), dz = fmaf(c.z, id, bi.z);
            const float sw = fmaf(a.w, is, bi.w), dw = fmaf(c.w, id, bi.w);
            acc += sx * bb.x * dx + sy * bb.y * dy + sz * bb.z * dz + sw * bb.w * dw;
        }
    }
    acc = warpReduceSum(acc);
    if (lane == 0) out[b] = acc;
}

// ---------------- launch ----------------
extern "C" void kernel_launch(void* const* d_in, const int* in_sizes, int n_in,
                              void* d_out, int out_size) {
    const float* node_emb = (const float*)d_in[0];
    const float* W        = (const float*)d_in[1];
    const float* bias     = (const float*)d_in[2];
    const float* a_src    = (const float*)d_in[3];
    const float* a_dst    = (const float*)d_in[4];
    const float* a_rel    = (const float*)d_in[5];
    const float* rel_feat = (const float*)d_in[6];
    const float* rel_emb  = (const float*)d_in[7];
    const idx_t* eidx     = (const idx_t*)d_in[8];
    const idx_t* etype    = (const idx_t*)d_in[9];
    const idx_t* src_ids  = (const idx_t*)d_in[10];
    const idx_t* rel_ids  = (const idx_t*)d_in[11];
    const idx_t* dst_ids  = (const idx_t*)d_in[12];
    float* scores = (float*)d_out;

    reset_kernel<<<(NN * NH + 255) / 256, 256>>>();
    mark_s_kernel<<<(2 * BB + 255) / 256, 256>>>(src_ids, dst_ids);
    init_out_kernel<<<2 * BB, 128>>>();
    build_list_kernel<<<(EE + 255) / 256, 256>>>(eidx);
    proj_kernel<<<IND, 128>>>(W, a_src, a_dst);
    svec_list_kernel<true><<<(NN + 7) / 8, 256>>>(node_emb);
    svec_list_kernel<false><<<(2 * BB + 7) / 8, 256>>>(node_emb);
    rel_dots_kernel<<<(NREL * NH + 7) / 8, 256>>>(rel_feat, a_rel);
    {
        dim3 grid((HIDD + 31) / 32, (IND + 31) / 32);
        wconv_kernel<<<grid, dim3(32, 8)>>>(W);
    }
    {
        cudaFuncSetAttribute(gemm_mma_kernel, cudaFuncAttributeMaxDynamicSharedMemorySize, GEMM_SMEM);
        dim3 grid(HIDD / BN, (NN + BM - 1) / BM);
        gemm_mma_kernel<<<grid, 256, GEMM_SMEM>>>(node_emb);
    }
    edge_all_kernel<<<(EE + 7) / 8, 256>>>(eidx, etype);
    distmult_kernel<<<(BB + 7) / 8, 256>>>(rel_emb, bias, src_ids, rel_ids, dst_ids, scores);
}